// round 4
// baseline (speedup 1.0000x reference)
#include <cuda_runtime.h>

#define NNODES 100000
#define NEDGES 1600000
#define NEG_SLOPE 0.2f
#define EPS_IN 1e-5f

typedef unsigned long long u64;

// ---------------- scratch ----------------
__device__ float g_xl[NNODES * 64];
__device__ float g_xr[NNODES * 64];
__device__ float g_h[NNODES * 64];
__device__ float g_skip[NNODES * 64];
__device__ float g_score[NEDGES];
__device__ int   g_esrc[NEDGES];
__device__ int   g_edsts[NEDGES];
__device__ int   g_eorig[NEDGES];
__device__ int   g_src[NEDGES];
__device__ int   g_dst[NEDGES];
__device__ int   g_deg[NNODES];
__device__ int   g_rowptr[NNODES + 1];
__device__ int   g_cursor[NNODES];
__device__ int   g_is64;
__device__ u64   g_wdup[7 * 4096];   // 7 weight mats as (w,w) pairs: [slot][k*64+c]

// ---------------- f32x2 helpers ----------------
__device__ __forceinline__ u64 pack2(float x, float y) {
    u64 r; asm("mov.b64 %0, {%1, %2};" : "=l"(r) : "f"(x), "f"(y)); return r;
}
__device__ __forceinline__ void unpack2(u64 v, float& x, float& y) {
    asm("mov.b64 {%0, %1}, %2;" : "=f"(x), "=f"(y) : "l"(v));
}
__device__ __forceinline__ u64 ffma2(u64 a, u64 b, u64 c) {
    u64 d; asm("fma.rn.f32x2 %0, %1, %2, %3;" : "=l"(d) : "l"(a), "l"(b), "l"(c));
    return d;
}

// ---------------- launch 1: detect dtype + zero deg + dup weights ----------------
__global__ void prep_kernel(const int* w,
                            const float* W0, const float* W1, const float* W2,
                            const float* W3, const float* W4, const float* W5,
                            const float* W6)
{
    int bid = blockIdx.x, tid = threadIdx.x;
    if (bid == 0 && tid < 32) {
        int z = (w[2 * tid + 1] == 0) ? 1 : 0;
        unsigned b = __ballot_sync(0xffffffffu, z != 0);
        if (tid == 0) g_is64 = (b == 0xffffffffu) ? 1 : 0;
    }
    int i = bid * 256 + tid;
    if (i < NNODES) g_deg[i] = 0;
    if (i < 7 * 4096) {
        const float* Ws[7] = {W0, W1, W2, W3, W4, W5, W6};
        int slot = i >> 12, r = i & 4095;
        int k = r >> 6, c = r & 63;
        float v = Ws[slot][c * 64 + k];
        g_wdup[(slot << 12) + (k << 6) + c] = pack2(v, v);
    }
}

// ---------------- launch 2: convert edge index + count degrees ----------------
__global__ void convert_count_kernel(const void* ei) {
    int e = blockIdx.x * blockDim.x + threadIdx.x;
    if (e >= NEDGES) return;
    int s, d;
    if (g_is64) {
        const long long* p = (const long long*)ei;
        s = (int)p[e]; d = (int)p[NEDGES + e];
    } else {
        const int* p = (const int*)ei;
        s = p[e]; d = p[NEDGES + e];
    }
    g_src[e] = s; g_dst[e] = d;
    atomicAdd(&g_deg[d], 1);
}

__global__ void scan_kernel() {
    __shared__ int part[1024];
    int tid = threadIdx.x;
    const int chunk = (NNODES + 1023) / 1024;
    int start = tid * chunk;
    int end = start + chunk; if (end > NNODES) end = NNODES;
    int s = 0;
    for (int i = start; i < end; i++) s += g_deg[i];
    part[tid] = s;
    __syncthreads();
    for (int off = 1; off < 1024; off <<= 1) {
        int v = (tid >= off) ? part[tid - off] : 0;
        __syncthreads();
        part[tid] += v;
        __syncthreads();
    }
    int base = (tid == 0) ? 0 : part[tid - 1];
    for (int i = start; i < end; i++) {
        g_rowptr[i] = base;
        g_cursor[i] = base;
        base += g_deg[i];
    }
    if (tid == 1023) g_rowptr[NNODES] = base;
}

__global__ void place_kernel() {
    int e = blockIdx.x * blockDim.x + threadIdx.x;
    if (e >= NEDGES) return;
    int dst = g_dst[e];
    int pos = atomicAdd(&g_cursor[dst], 1);
    g_esrc[pos] = g_src[e];
    g_edsts[pos] = dst;
    g_eorig[pos] = e;
}

// ---------------- tiled GEMM core ----------------
// Tile 128 rows x 64 cols, K=64, 256 threads.
// A stored in smem as row-pairs: apair[k][j] = (A[row j][k], A[row j+64][k]), j=0..63.
// W staged as pre-duplicated pairs from g_wdup.
// Thread(lane,wid): accA[p] = cols wid*8+p, rows (lane, lane+64); accB[p] rows (lane+32, lane+96).
// smem layout (u64/floats):
//   wdup_s : 4096 u64  (32768 B)
//   apair  : 64*66 u64 (33792 B)
//   m_s    : 128*68 f  (34816 B)  [MODE 1 only]
//   sp     : 128*9  f  ( 4608 B)  [MODE 1 only]
#define SMEM_LIN   (32768 + 33792)
#define SMEM_SCORE (32768 + 33792 + 34816 + 4608)

__device__ __forceinline__ void gemm_compute(const u64* apair, const u64* wdup_s,
                                             int lane, int wid,
                                             u64 accA[8], u64 accB[8])
{
    #pragma unroll 4
    for (int k = 0; k < 64; k++) {
        u64 a01 = apair[k * 66 + lane];
        u64 a23 = apair[k * 66 + lane + 32];
        const ulonglong2* wp = (const ulonglong2*)(wdup_s + k * 64 + wid * 8);
        ulonglong2 w0 = wp[0], w1 = wp[1], w2 = wp[2], w3 = wp[3];
        accA[0] = ffma2(a01, w0.x, accA[0]); accA[1] = ffma2(a01, w0.y, accA[1]);
        accA[2] = ffma2(a01, w1.x, accA[2]); accA[3] = ffma2(a01, w1.y, accA[3]);
        accA[4] = ffma2(a01, w2.x, accA[4]); accA[5] = ffma2(a01, w2.y, accA[5]);
        accA[6] = ffma2(a01, w3.x, accA[6]); accA[7] = ffma2(a01, w3.y, accA[7]);
        accB[0] = ffma2(a23, w0.x, accB[0]); accB[1] = ffma2(a23, w0.y, accB[1]);
        accB[2] = ffma2(a23, w1.x, accB[2]); accB[3] = ffma2(a23, w1.y, accB[3]);
        accB[4] = ffma2(a23, w2.x, accB[4]); accB[5] = ffma2(a23, w2.y, accB[5]);
        accB[6] = ffma2(a23, w3.x, accB[6]); accB[7] = ffma2(a23, w3.y, accB[7]);
    }
}

// node linears: up to 3 weight sets over one staged A tile
__global__ void __launch_bounds__(256, 2) lin_kernel(
    const float* Aext, int asel, int nsets, int slot0,
    const float* __restrict__ b0, const float* __restrict__ b1,
    const float* __restrict__ b2, int nrows)
{
    extern __shared__ __align__(16) char smraw[];
    u64* wdup_s = (u64*)smraw;
    u64* apair  = wdup_s + 4096;
    float* apairf = (float*)apair;

    const float* A = (asel == 1) ? g_h : Aext;
    int tid = threadIdx.x;
    int lane = tid & 31, wid = tid >> 5;
    int r0 = blockIdx.x * 128;

    // stage A as row-pairs
    for (int it = wid; it < 128; it += 8) {
        int q = it & 31, gch = it >> 5;
        int rl = q * 4 + (lane & 3);
        int rr = r0 + rl;
        int row = (rr < nrows) ? rr : 0;
        int k = gch * 16 + 2 * (lane >> 2);
        float2 v = *(const float2*)(A + (size_t)row * 64 + k);
        int j = rl & 63, half = rl >> 6;
        apairf[(k * 66 + j) * 2 + half]       = v.x;
        apairf[((k + 1) * 66 + j) * 2 + half] = v.y;
    }

    const float* bs[3] = {b0, b1, b2};
    float* outs[3] = {g_xl, g_xr, g_skip};

    for (int s = 0; s < nsets; s++) {
        __syncthreads();
        const u64* wg = g_wdup + ((size_t)(slot0 + s) << 12);
        for (int i = tid; i < 4096; i += 256) wdup_s[i] = wg[i];
        __syncthreads();

        u64 accA[8], accB[8];
        const float* vb = bs[s];
        #pragma unroll
        for (int p = 0; p < 8; p++) {
            float bv = vb[wid * 8 + p];
            accA[p] = pack2(bv, bv);
            accB[p] = accA[p];
        }

        gemm_compute(apair, wdup_s, lane, wid, accA, accB);

        float* O = outs[s];
        float rA0[8], rA1[8], rB0[8], rB1[8];
        #pragma unroll
        for (int p = 0; p < 8; p++) {
            unpack2(accA[p], rA0[p], rA1[p]);
            unpack2(accB[p], rB0[p], rB1[p]);
        }
        int c0 = wid * 8;
        int r;
        r = r0 + lane;
        if (r < nrows) {
            *(float4*)(O + (size_t)r * 64 + c0)     = make_float4(rA0[0], rA0[1], rA0[2], rA0[3]);
            *(float4*)(O + (size_t)r * 64 + c0 + 4) = make_float4(rA0[4], rA0[5], rA0[6], rA0[7]);
        }
        r = r0 + lane + 32;
        if (r < nrows) {
            *(float4*)(O + (size_t)r * 64 + c0)     = make_float4(rB0[0], rB0[1], rB0[2], rB0[3]);
            *(float4*)(O + (size_t)r * 64 + c0 + 4) = make_float4(rB0[4], rB0[5], rB0[6], rB0[7]);
        }
        r = r0 + lane + 64;
        if (r < nrows) {
            *(float4*)(O + (size_t)r * 64 + c0)     = make_float4(rA1[0], rA1[1], rA1[2], rA1[3]);
            *(float4*)(O + (size_t)r * 64 + c0 + 4) = make_float4(rA1[4], rA1[5], rA1[6], rA1[7]);
        }
        r = r0 + lane + 96;
        if (r < nrows) {
            *(float4*)(O + (size_t)r * 64 + c0)     = make_float4(rB1[0], rB1[1], rB1[2], rB1[3]);
            *(float4*)(O + (size_t)r * 64 + c0 + 4) = make_float4(rB1[4], rB1[5], rB1[6], rB1[7]);
        }
    }
}

// edge score: m = xl[src]+xr[dst] + ea@We^T ; score = dot(lrelu(m), att)
__global__ void __launch_bounds__(256, 2) score_kernel(
    const float* __restrict__ ea, int slot, const float* __restrict__ att)
{
    extern __shared__ __align__(16) char smraw[];
    u64* wdup_s = (u64*)smraw;
    u64* apair  = wdup_s + 4096;
    float* apairf = (float*)apair;
    float* m_s = (float*)(apair + 64 * 66);   // [128][68]
    float* sp  = m_s + 128 * 68;              // [128][9]

    int tid = threadIdx.x;
    int lane = tid & 31, wid = tid >> 5;
    int r0 = blockIdx.x * 128;

    // stage W (pre-duplicated, coalesced)
    const u64* wg = g_wdup + ((size_t)slot << 12);
    for (int i = tid; i < 4096; i += 256) wdup_s[i] = wg[i];

    // stage A (gathered edge_attr rows) as row-pairs
    for (int it = wid; it < 128; it += 8) {
        int q = it & 31, gch = it >> 5;
        int rl = q * 4 + (lane & 3);
        int orig = g_eorig[r0 + rl];
        int k = gch * 16 + 2 * (lane >> 2);
        float2 v = *(const float2*)(ea + (size_t)orig * 64 + k);
        int j = rl & 63, half = rl >> 6;
        apairf[(k * 66 + j) * 2 + half]       = v.x;
        apairf[((k + 1) * 66 + j) * 2 + half] = v.y;
    }

    // stage init: m_s[r] = xl[src] + xr[dst]
    for (int r = wid; r < 128; r += 8) {
        int rr = r0 + r;
        int s = g_esrc[rr], dd = g_edsts[rr];
        float2 va = *(const float2*)(g_xl + (size_t)s * 64 + 2 * lane);
        float2 vc = *(const float2*)(g_xr + (size_t)dd * 64 + 2 * lane);
        float2 o; o.x = va.x + vc.x; o.y = va.y + vc.y;
        *(float2*)(m_s + r * 68 + 2 * lane) = o;
    }
    __syncthreads();

    u64 accA[8], accB[8];
    int c0 = wid * 8;
    #pragma unroll
    for (int p = 0; p < 8; p++) {
        accA[p] = pack2(m_s[lane * 68 + c0 + p],        m_s[(lane + 64) * 68 + c0 + p]);
        accB[p] = pack2(m_s[(lane + 32) * 68 + c0 + p], m_s[(lane + 96) * 68 + c0 + p]);
    }

    gemm_compute(apair, wdup_s, lane, wid, accA, accB);

    float av[8];
    #pragma unroll
    for (int p = 0; p < 8; p++) av[p] = att[c0 + p];

    float s0 = 0.f, s1 = 0.f, s2 = 0.f, s3 = 0.f;
    #pragma unroll
    for (int p = 0; p < 8; p++) {
        float x0, x1, y0, y1;
        unpack2(accA[p], x0, x1);
        unpack2(accB[p], y0, y1);
        s0 += ((x0 > 0.f) ? x0 : NEG_SLOPE * x0) * av[p];
        s1 += ((y0 > 0.f) ? y0 : NEG_SLOPE * y0) * av[p];
        s2 += ((x1 > 0.f) ? x1 : NEG_SLOPE * x1) * av[p];
        s3 += ((y1 > 0.f) ? y1 : NEG_SLOPE * y1) * av[p];
    }
    sp[lane * 9 + wid]        = s0;
    sp[(lane + 32) * 9 + wid] = s1;
    sp[(lane + 64) * 9 + wid] = s2;
    sp[(lane + 96) * 9 + wid] = s3;
    __syncthreads();
    if (tid < 128) {
        float s = 0.f;
        #pragma unroll
        for (int w = 0; w < 8; w++) s += sp[tid * 9 + w];
        g_score[r0 + tid] = s;
    }
}

// ---------------- per-node softmax + gather + relu + instnorm ----------------
__global__ void aggregate_kernel(const float* __restrict__ bo,
                                 int useskip, float* out_ext)
{
    __shared__ float s_a[8][32];
    __shared__ int   s_s[8][32];
    float* out = out_ext ? out_ext : g_h;
    int tid = threadIdx.x;
    int w = tid >> 5, l = tid & 31;
    int n = blockIdx.x * 8 + w;
    if (n >= NNODES) return;

    int r0 = g_rowptr[n], r1 = g_rowptr[n + 1];

    float mx = -3.402823466e38f;
    for (int i = r0 + l; i < r1; i += 32) mx = fmaxf(mx, g_score[i]);
    #pragma unroll
    for (int o = 16; o > 0; o >>= 1) mx = fmaxf(mx, __shfl_xor_sync(0xffffffffu, mx, o));

    float ss = 0.f;
    for (int i = r0 + l; i < r1; i += 32) ss += __expf(g_score[i] - mx);
    #pragma unroll
    for (int o = 16; o > 0; o >>= 1) ss += __shfl_xor_sync(0xffffffffu, ss, o);
    float inv = 1.f / (ss + 1e-16f);

    float acc0 = 0.f, acc1 = 0.f;
    for (int c = r0; c < r1; c += 32) {
        int i = c + l;
        if (i < r1) {
            s_a[w][l] = __expf(g_score[i] - mx) * inv;
            s_s[w][l] = g_esrc[i];
        }
        __syncwarp();
        int cnt = r1 - c; if (cnt > 32) cnt = 32;
        #pragma unroll 4
        for (int j = 0; j < cnt; j++) {
            float a = s_a[w][j];
            const float* xs = g_xl + (size_t)s_s[w][j] * 64;
            acc0 += a * __ldg(xs + l);
            acc1 += a * __ldg(xs + l + 32);
        }
        __syncwarp();
    }

    float v0 = acc0 + bo[l];
    float v1 = acc1 + bo[l + 32];
    if (useskip) {
        v0 += g_skip[(size_t)n * 64 + l];
        v1 += g_skip[(size_t)n * 64 + l + 32];
    }
    v0 = fmaxf(v0, 0.f);
    v1 = fmaxf(v1, 0.f);

    float t = v0 + v1;
    #pragma unroll
    for (int o = 16; o > 0; o >>= 1) t += __shfl_xor_sync(0xffffffffu, t, o);
    float mu = t * (1.f / 64.f);
    float d0 = v0 - mu, d1 = v1 - mu;
    float q = d0 * d0 + d1 * d1;
    #pragma unroll
    for (int o = 16; o > 0; o >>= 1) q += __shfl_xor_sync(0xffffffffu, q, o);
    float sc = rsqrtf(q * (1.f / 64.f) + EPS_IN);

    out[(size_t)n * 64 + l]      = d0 * sc;
    out[(size_t)n * 64 + l + 32] = d1 * sc;
}

// ---------------- launch ----------------
extern "C" void kernel_launch(void* const* d_in, const int* in_sizes, int n_in,
                              void* d_out, int out_size) {
    const float* x     = (const float*)d_in[0];
    const void*  ei    = d_in[1];
    const float* ea    = (const float*)d_in[2];
    const float* Wl1   = (const float*)d_in[3];
    const float* bl1   = (const float*)d_in[4];
    const float* Wr1   = (const float*)d_in[5];
    const float* br1   = (const float*)d_in[6];
    const float* We1   = (const float*)d_in[7];
    const float* att1  = (const float*)d_in[8];
    const float* bo1   = (const float*)d_in[9];
    const float* Wl2   = (const float*)d_in[10];
    const float* bl2   = (const float*)d_in[11];
    const float* Wr2   = (const float*)d_in[12];
    const float* br2   = (const float*)d_in[13];
    const float* We2   = (const float*)d_in[14];
    const float* att2  = (const float*)d_in[15];
    const float* bo2   = (const float*)d_in[16];
    const float* Wskip = (const float*)d_in[17];
    const float* bskip = (const float*)d_in[18];
    float* out = (float*)d_out;

    static int inited = 0;
    if (!inited) {
        cudaFuncSetAttribute(lin_kernel,   cudaFuncAttributeMaxDynamicSharedMemorySize, SMEM_LIN);
        cudaFuncSetAttribute(score_kernel, cudaFuncAttributeMaxDynamicSharedMemorySize, SMEM_SCORE);
        inited = 1;
    }

    const int EB = (NEDGES + 255) / 256;
    const int NT = (NNODES + 127) / 128;
    const int ET = NEDGES / 128;

    // slots: 0=Wl1 1=Wr1 2=Wskip 3=We1 4=Wl2 5=Wr2 6=We2
    prep_kernel<<<391, 256>>>((const int*)ei, Wl1, Wr1, Wskip, We1, Wl2, Wr2, We2);  // 1
    convert_count_kernel<<<EB, 256>>>(ei);                                            // 2
    scan_kernel<<<1, 1024>>>();                                                       // 3
    lin_kernel<<<NT, 256, SMEM_LIN>>>(x, 0, 3, 0, bl1, br1, bskip, NNODES);           // 4 (profiled)
    place_kernel<<<EB, 256>>>();                                                      // 5
    score_kernel<<<ET, 256, SMEM_SCORE>>>(ea, 3, att1);                               // 6
    aggregate_kernel<<<(NNODES + 7) / 8, 256>>>(bo1, 0, nullptr);                     // 7
    lin_kernel<<<NT, 256, SMEM_LIN>>>(nullptr, 1, 2, 4, bl2, br2, nullptr, NNODES);   // 8
    score_kernel<<<ET, 256, SMEM_SCORE>>>(ea, 6, att2);                               // 9
    aggregate_kernel<<<(NNODES + 7) / 8, 256>>>(bo2, 1, out);                         // 10
}

// round 6
// speedup vs baseline: 1.9865x; 1.9865x over previous
#include <cuda_runtime.h>
#include <cuda_bf16.h>
#include <cstdint>

#define NNODES 100000
#define NEDGES 1600000
#define NEG_SLOPE 0.2f
#define EPS_IN 1e-5f

typedef unsigned long long u64;

// ---------------- scratch ----------------
__device__ float g_xl[NNODES * 64];
__device__ float g_xr[NNODES * 64];
__device__ float g_h[NNODES * 64];
__device__ float g_skip[NNODES * 64];
__device__ float g_score[NEDGES];
__device__ int   g_esrc[NEDGES];
__device__ int   g_edsts[NEDGES];
__device__ int   g_eorig[NEDGES];
__device__ int   g_src[NEDGES];
__device__ int   g_dst[NEDGES];
__device__ int   g_deg[NNODES];
__device__ int   g_rowptr[NNODES + 1];
__device__ int   g_cursor[NNODES];
__device__ int   g_is64;
__device__ u64   g_wdup[7 * 4096];                 // fp32 (w,w) pairs for lin kernels
__device__ __nv_bfloat16 g_wb16[2 * 2 * 64 * 72];  // [layer][hi/lo][n=64][k padded 72]

// ---------------- f32x2 helpers ----------------
__device__ __forceinline__ u64 pack2(float x, float y) {
    u64 r; asm("mov.b64 %0, {%1, %2};" : "=l"(r) : "f"(x), "f"(y)); return r;
}
__device__ __forceinline__ void unpack2(u64 v, float& x, float& y) {
    asm("mov.b64 {%0, %1}, %2;" : "=f"(x), "=f"(y) : "l"(v));
}
__device__ __forceinline__ u64 ffma2(u64 a, u64 b, u64 c) {
    u64 d; asm("fma.rn.f32x2 %0, %1, %2, %3;" : "=l"(d) : "l"(a), "l"(b), "l"(c));
    return d;
}

__device__ __forceinline__ uint32_t smem_u32(const void* p) {
    uint32_t a;
    asm("{ .reg .u64 t; cvta.to.shared.u64 t, %1; cvt.u32.u64 %0, t; }" : "=r"(a) : "l"(p));
    return a;
}

__device__ __forceinline__ void ldsm_x4(uint32_t& r0, uint32_t& r1, uint32_t& r2, uint32_t& r3,
                                        uint32_t addr) {
    asm volatile("ldmatrix.sync.aligned.m8n8.x4.shared.b16 {%0,%1,%2,%3}, [%4];"
                 : "=r"(r0), "=r"(r1), "=r"(r2), "=r"(r3) : "r"(addr));
}

__device__ __forceinline__ void mma_bf16(float& c0, float& c1, float& c2, float& c3,
                                         uint32_t a0, uint32_t a1, uint32_t a2, uint32_t a3,
                                         uint32_t b0, uint32_t b1) {
    asm volatile(
        "mma.sync.aligned.m16n8k16.row.col.f32.bf16.bf16.f32 "
        "{%0,%1,%2,%3}, {%4,%5,%6,%7}, {%8,%9}, {%0,%1,%2,%3};"
        : "+f"(c0), "+f"(c1), "+f"(c2), "+f"(c3)
        : "r"(a0), "r"(a1), "r"(a2), "r"(a3), "r"(b0), "r"(b1));
}

// ---------------- launch 1: detect dtype + zero deg + dup weights + bf16 We images ----------------
__global__ void prep_kernel(const int* w,
                            const float* W0, const float* W1, const float* W2,
                            const float* W3, const float* W4, const float* W5,
                            const float* W6)
{
    int bid = blockIdx.x, tid = threadIdx.x;
    if (bid == 0 && tid < 32) {
        int z = (w[2 * tid + 1] == 0) ? 1 : 0;
        unsigned b = __ballot_sync(0xffffffffu, z != 0);
        if (tid == 0) g_is64 = (b == 0xffffffffu) ? 1 : 0;
    }
    int i = bid * 256 + tid;
    if (i < NNODES) g_deg[i] = 0;
    if (i < 7 * 4096) {
        const float* Ws[7] = {W0, W1, W2, W3, W4, W5, W6};
        int slot = i >> 12, r = i & 4095;
        int k = r >> 6, c = r & 63;
        float v = Ws[slot][c * 64 + k];
        g_wdup[(slot << 12) + (k << 6) + c] = pack2(v, v);
    }
    if (i < 2 * 4096) {
        const float* Wsrc = (i < 4096) ? W3 : W6;   // We1, We2
        int layer = i >> 12, r = i & 4095;
        int n = r >> 6, k = r & 63;
        float v = Wsrc[n * 64 + k];
        __nv_bfloat16 hi = __float2bfloat16_rn(v);
        __nv_bfloat16 lo = __float2bfloat16_rn(v - __bfloat162float(hi));
        g_wb16[((layer * 2 + 0) * 64 + n) * 72 + k] = hi;
        g_wb16[((layer * 2 + 1) * 64 + n) * 72 + k] = lo;
    }
}

// ---------------- launch 2: convert edge index + count ----------------
__global__ void convert_count_kernel(const void* ei) {
    int e = blockIdx.x * blockDim.x + threadIdx.x;
    if (e >= NEDGES) return;
    int s, d;
    if (g_is64) {
        const long long* p = (const long long*)ei;
        s = (int)p[e]; d = (int)p[NEDGES + e];
    } else {
        const int* p = (const int*)ei;
        s = p[e]; d = p[NEDGES + e];
    }
    g_src[e] = s; g_dst[e] = d;
    atomicAdd(&g_deg[d], 1);
}

__global__ void scan_kernel() {
    __shared__ int part[1024];
    int tid = threadIdx.x;
    const int chunk = (NNODES + 1023) / 1024;
    int start = tid * chunk;
    int end = start + chunk; if (end > NNODES) end = NNODES;
    int s = 0;
    for (int i = start; i < end; i++) s += g_deg[i];
    part[tid] = s;
    __syncthreads();
    for (int off = 1; off < 1024; off <<= 1) {
        int v = (tid >= off) ? part[tid - off] : 0;
        __syncthreads();
        part[tid] += v;
        __syncthreads();
    }
    int base = (tid == 0) ? 0 : part[tid - 1];
    for (int i = start; i < end; i++) {
        g_rowptr[i] = base;
        g_cursor[i] = base;
        base += g_deg[i];
    }
    if (tid == 1023) g_rowptr[NNODES] = base;
}

__global__ void place_kernel() {
    int e = blockIdx.x * blockDim.x + threadIdx.x;
    if (e >= NEDGES) return;
    int dst = g_dst[e];
    int pos = atomicAdd(&g_cursor[dst], 1);
    g_esrc[pos] = g_src[e];
    g_edsts[pos] = dst;
    g_eorig[pos] = e;
}

// ---------------- node linears (fp32 f32x2 path, up to 3 sets) ----------------
#define SMEM_LIN (32768 + 33792)

__device__ __forceinline__ void gemm_compute(const u64* apair, const u64* wdup_s,
                                             int lane, int wid,
                                             u64 accA[8], u64 accB[8])
{
    #pragma unroll 4
    for (int k = 0; k < 64; k++) {
        u64 a01 = apair[k * 66 + lane];
        u64 a23 = apair[k * 66 + lane + 32];
        const ulonglong2* wp = (const ulonglong2*)(wdup_s + k * 64 + wid * 8);
        ulonglong2 w0 = wp[0], w1 = wp[1], w2 = wp[2], w3 = wp[3];
        accA[0] = ffma2(a01, w0.x, accA[0]); accA[1] = ffma2(a01, w0.y, accA[1]);
        accA[2] = ffma2(a01, w1.x, accA[2]); accA[3] = ffma2(a01, w1.y, accA[3]);
        accA[4] = ffma2(a01, w2.x, accA[4]); accA[5] = ffma2(a01, w2.y, accA[5]);
        accA[6] = ffma2(a01, w3.x, accA[6]); accA[7] = ffma2(a01, w3.y, accA[7]);
        accB[0] = ffma2(a23, w0.x, accB[0]); accB[1] = ffma2(a23, w0.y, accB[1]);
        accB[2] = ffma2(a23, w1.x, accB[2]); accB[3] = ffma2(a23, w1.y, accB[3]);
        accB[4] = ffma2(a23, w2.x, accB[4]); accB[5] = ffma2(a23, w2.y, accB[5]);
        accB[6] = ffma2(a23, w3.x, accB[6]); accB[7] = ffma2(a23, w3.y, accB[7]);
    }
}

__global__ void __launch_bounds__(256, 2) lin_kernel(
    const float* Aext, int asel, int nsets, int slot0,
    const float* __restrict__ b0, const float* __restrict__ b1,
    const float* __restrict__ b2, int nrows)
{
    extern __shared__ __align__(16) char smraw[];
    u64* wdup_s = (u64*)smraw;
    u64* apair  = wdup_s + 4096;
    float* apairf = (float*)apair;

    const float* A = (asel == 1) ? g_h : Aext;
    int tid = threadIdx.x;
    int lane = tid & 31, wid = tid >> 5;
    int r0 = blockIdx.x * 128;

    for (int it = wid; it < 128; it += 8) {
        int q = it & 31, gch = it >> 5;
        int rl = q * 4 + (lane & 3);
        int rr = r0 + rl;
        int row = (rr < nrows) ? rr : 0;
        int k = gch * 16 + 2 * (lane >> 2);
        float2 v = *(const float2*)(A + (size_t)row * 64 + k);
        int j = rl & 63, half = rl >> 6;
        apairf[(k * 66 + j) * 2 + half]       = v.x;
        apairf[((k + 1) * 66 + j) * 2 + half] = v.y;
    }

    const float* bs[3] = {b0, b1, b2};
    float* outs[3] = {g_xl, g_xr, g_skip};

    for (int s = 0; s < nsets; s++) {
        __syncthreads();
        const u64* wg = g_wdup + ((size_t)(slot0 + s) << 12);
        for (int i = tid; i < 4096; i += 256) wdup_s[i] = wg[i];
        __syncthreads();

        u64 accA[8], accB[8];
        const float* vb = bs[s];
        #pragma unroll
        for (int p = 0; p < 8; p++) {
            float bv = vb[wid * 8 + p];
            accA[p] = pack2(bv, bv);
            accB[p] = accA[p];
        }

        gemm_compute(apair, wdup_s, lane, wid, accA, accB);

        float* O = outs[s];
        float rA0[8], rA1[8], rB0[8], rB1[8];
        #pragma unroll
        for (int p = 0; p < 8; p++) {
            unpack2(accA[p], rA0[p], rA1[p]);
            unpack2(accB[p], rB0[p], rB1[p]);
        }
        int c0 = wid * 8;
        int r;
        r = r0 + lane;
        if (r < nrows) {
            *(float4*)(O + (size_t)r * 64 + c0)     = make_float4(rA0[0], rA0[1], rA0[2], rA0[3]);
            *(float4*)(O + (size_t)r * 64 + c0 + 4) = make_float4(rA0[4], rA0[5], rA0[6], rA0[7]);
        }
        r = r0 + lane + 32;
        if (r < nrows) {
            *(float4*)(O + (size_t)r * 64 + c0)     = make_float4(rB0[0], rB0[1], rB0[2], rB0[3]);
            *(float4*)(O + (size_t)r * 64 + c0 + 4) = make_float4(rB0[4], rB0[5], rB0[6], rB0[7]);
        }
        r = r0 + lane + 64;
        if (r < nrows) {
            *(float4*)(O + (size_t)r * 64 + c0)     = make_float4(rA1[0], rA1[1], rA1[2], rA1[3]);
            *(float4*)(O + (size_t)r * 64 + c0 + 4) = make_float4(rA1[4], rA1[5], rA1[6], rA1[7]);
        }
        r = r0 + lane + 96;
        if (r < nrows) {
            *(float4*)(O + (size_t)r * 64 + c0)     = make_float4(rB1[0], rB1[1], rB1[2], rB1[3]);
            *(float4*)(O + (size_t)r * 64 + c0 + 4) = make_float4(rB1[4], rB1[5], rB1[6], rB1[7]);
        }
    }
}

// ---------------- HMMA (mma.sync bf16) edge score ----------------
// Tile 128 edges x 64 cols, K=64. 3 passes: Ahi*Bhi + Ahi*Blo + Alo*Bhi, fp32 acc.
// smem byte offsets:
#define O_ORIG 0
#define O_ATT  512
#define O_MIN  768                        // 128 rows x 68 floats
#define O_AHI  (O_MIN + 128*68*4)         // 35584; 128 x 72 bf16 (144B rows)
#define O_ALO  (O_AHI + 18432)
#define O_BHI  (O_ALO + 18432)            // 64 x 72 bf16 hi
#define O_BLO  (O_BHI + 9216)
#define SMEM_SCORE (O_BLO + 9216)         // 90880 B

__global__ void __launch_bounds__(128, 2) score_mma_kernel(
    const float* __restrict__ ea, int layer, const float* __restrict__ att)
{
    extern __shared__ __align__(16) char sm[];
    int*   s_orig = (int*)(sm + O_ORIG);
    float* s_att  = (float*)(sm + O_ATT);
    float* s_min  = (float*)(sm + O_MIN);
    uint32_t sb = smem_u32(sm);

    int tid = threadIdx.x;
    int wid = tid >> 5, lane = tid & 31;
    int r0 = blockIdx.x * 128;

    s_orig[tid] = g_eorig[r0 + tid];
    if (tid < 64) s_att[tid] = att[tid];

    // stage B images (hi+lo, padded): 18432B coalesced
    {
        const uint4* wp = (const uint4*)((const char*)g_wb16 + layer * 18432);
        uint4* bsm = (uint4*)(sm + O_BHI);
        #pragma unroll
        for (int i = 0; i < 9; i++) bsm[tid + 128 * i] = wp[tid + 128 * i];
    }
    __syncthreads();   // s_orig ready

    // stage A: gather + bf16 hi/lo split
    #pragma unroll
    for (int i = 0; i < 8; i++) {
        int u = tid + (i << 7);
        int row = u >> 3, ch = u & 7;
        int orig = s_orig[row];
        const float4* src = (const float4*)(ea + (size_t)orig * 64 + ch * 8);
        float4 v0 = src[0], v1 = src[1];
        float vv[8] = {v0.x, v0.y, v0.z, v0.w, v1.x, v1.y, v1.z, v1.w};
        uint32_t hbits[4], lbits[4];
        #pragma unroll
        for (int j = 0; j < 4; j++) {
            __nv_bfloat16 h0 = __float2bfloat16_rn(vv[2 * j]);
            __nv_bfloat16 h1 = __float2bfloat16_rn(vv[2 * j + 1]);
            __nv_bfloat16 l0 = __float2bfloat16_rn(vv[2 * j]     - __bfloat162float(h0));
            __nv_bfloat16 l1 = __float2bfloat16_rn(vv[2 * j + 1] - __bfloat162float(h1));
            hbits[j] = (uint32_t)__bfloat16_as_ushort(h0) | ((uint32_t)__bfloat16_as_ushort(h1) << 16);
            lbits[j] = (uint32_t)__bfloat16_as_ushort(l0) | ((uint32_t)__bfloat16_as_ushort(l1) << 16);
        }
        int off = row * 144 + ch * 16;
        *(uint4*)(sm + O_AHI + off) = make_uint4(hbits[0], hbits[1], hbits[2], hbits[3]);
        *(uint4*)(sm + O_ALO + off) = make_uint4(lbits[0], lbits[1], lbits[2], lbits[3]);
    }

    // stage m_init = xl[src] + xr[dst]
    #pragma unroll
    for (int i = 0; i < 16; i++) {
        int u = tid + (i << 7);
        int row = u >> 4, c4 = u & 15;
        int rr = r0 + row;
        int s = g_esrc[rr], d = g_edsts[rr];
        float4 a = *(const float4*)(g_xl + (size_t)s * 64 + c4 * 4);
        float4 b = *(const float4*)(g_xr + (size_t)d * 64 + c4 * 4);
        *(float4*)(s_min + row * 68 + c4 * 4) =
            make_float4(a.x + b.x, a.y + b.y, a.z + b.z, a.w + b.w);
    }
    __syncthreads();

    // MMA: warp handles rows wid*32 .. +31
    float acc[2][8][4];
    #pragma unroll
    for (int mi = 0; mi < 2; mi++)
        #pragma unroll
        for (int nj = 0; nj < 8; nj++)
            #pragma unroll
            for (int c = 0; c < 4; c++) acc[mi][nj][c] = 0.f;

    #pragma unroll
    for (int pass = 0; pass < 3; pass++) {
        uint32_t Ab = sb + ((pass < 2) ? O_AHI : O_ALO);
        uint32_t Bb = sb + ((pass == 1) ? O_BLO : O_BHI);
        #pragma unroll
        for (int kb = 0; kb < 4; kb++) {
            uint32_t a[2][4];
            #pragma unroll
            for (int mi = 0; mi < 2; mi++) {
                int row = wid * 32 + mi * 16 + (lane & 15);
                int k = kb * 16 + ((lane & 16) ? 8 : 0);
                ldsm_x4(a[mi][0], a[mi][1], a[mi][2], a[mi][3], Ab + row * 144 + k * 2);
            }
            #pragma unroll
            for (int njp = 0; njp < 4; njp++) {
                int n = njp * 16 + ((lane & 16) ? 8 : 0) + (lane & 7);
                int k = kb * 16 + ((lane & 8) ? 8 : 0);
                uint32_t b0, b1, b2, b3;
                ldsm_x4(b0, b1, b2, b3, Bb + n * 144 + k * 2);
                #pragma unroll
                for (int mi = 0; mi < 2; mi++) {
                    mma_bf16(acc[mi][2 * njp][0], acc[mi][2 * njp][1],
                             acc[mi][2 * njp][2], acc[mi][2 * njp][3],
                             a[mi][0], a[mi][1], a[mi][2], a[mi][3], b0, b1);
                    mma_bf16(acc[mi][2 * njp + 1][0], acc[mi][2 * njp + 1][1],
                             acc[mi][2 * njp + 1][2], acc[mi][2 * njp + 1][3],
                             a[mi][0], a[mi][1], a[mi][2], a[mi][3], b2, b3);
                }
            }
        }
    }

    // epilogue: add m_init, leaky-relu, dot with att, per-row reduce
    int q = lane >> 2, r4 = lane & 3;
    float psum[4] = {0.f, 0.f, 0.f, 0.f};
    #pragma unroll
    for (int mi = 0; mi < 2; mi++) {
        int rowA = wid * 32 + mi * 16 + q;
        #pragma unroll
        for (int nj = 0; nj < 8; nj++) {
            int n = nj * 8 + 2 * r4;
            float a0 = s_att[n], a1 = s_att[n + 1];
            float2 m0 = *(const float2*)(s_min + rowA * 68 + n);
            float2 m1 = *(const float2*)(s_min + (rowA + 8) * 68 + n);
            float v;
            v = acc[mi][nj][0] + m0.x; psum[2 * mi]     += fmaxf(v, NEG_SLOPE * v) * a0;
            v = acc[mi][nj][1] + m0.y; psum[2 * mi]     += fmaxf(v, NEG_SLOPE * v) * a1;
            v = acc[mi][nj][2] + m1.x; psum[2 * mi + 1] += fmaxf(v, NEG_SLOPE * v) * a0;
            v = acc[mi][nj][3] + m1.y; psum[2 * mi + 1] += fmaxf(v, NEG_SLOPE * v) * a1;
        }
    }
    #pragma unroll
    for (int j = 0; j < 4; j++) {
        psum[j] += __shfl_xor_sync(0xffffffffu, psum[j], 1);
        psum[j] += __shfl_xor_sync(0xffffffffu, psum[j], 2);
    }
    if (r4 == 0) {
        int base = r0 + wid * 32 + q;
        g_score[base]      = psum[0];
        g_score[base + 8]  = psum[1];
        g_score[base + 16] = psum[2];
        g_score[base + 24] = psum[3];
    }
}

// ---------------- per-node softmax + gather + relu + instnorm ----------------
__global__ void aggregate_kernel(const float* __restrict__ bo,
                                 int useskip, float* out_ext)
{
    __shared__ float s_a[8][32];
    __shared__ int   s_s[8][32];
    float* out = out_ext ? out_ext : g_h;
    int tid = threadIdx.x;
    int w = tid >> 5, l = tid & 31;
    int n = blockIdx.x * 8 + w;
    if (n >= NNODES) return;

    int r0 = g_rowptr[n], r1 = g_rowptr[n + 1];

    float mx = -3.402823466e38f;
    for (int i = r0 + l; i < r1; i += 32) mx = fmaxf(mx, g_score[i]);
    #pragma unroll
    for (int o = 16; o > 0; o >>= 1) mx = fmaxf(mx, __shfl_xor_sync(0xffffffffu, mx, o));

    float ss = 0.f;
    for (int i = r0 + l; i < r1; i += 32) ss += __expf(g_score[i] - mx);
    #pragma unroll
    for (int o = 16; o > 0; o >>= 1) ss += __shfl_xor_sync(0xffffffffu, ss, o);
    float inv = 1.f / (ss + 1e-16f);

    float acc0 = 0.f, acc1 = 0.f;
    for (int c = r0; c < r1; c += 32) {
        int i = c + l;
        if (i < r1) {
            s_a[w][l] = __expf(g_score[i] - mx) * inv;
            s_s[w][l] = g_esrc[i];
        }
        __syncwarp();
        int cnt = r1 - c; if (cnt > 32) cnt = 32;
        #pragma unroll 4
        for (int j = 0; j < cnt; j++) {
            float a = s_a[w][j];
            const float* xs = g_xl + (size_t)s_s[w][j] * 64;
            acc0 += a * __ldg(xs + l);
            acc1 += a * __ldg(xs + l + 32);
        }
        __syncwarp();
    }

    float v0 = acc0 + bo[l];
    float v1 = acc1 + bo[l + 32];
    if (useskip) {
        v0 += g_skip[(size_t)n * 64 + l];
        v1 += g_skip[(size_t)n * 64 + l + 32];
    }
    v0 = fmaxf(v0, 0.f);
    v1 = fmaxf(v1, 0.f);

    float t = v0 + v1;
    #pragma unroll
    for (int o = 16; o > 0; o >>= 1) t += __shfl_xor_sync(0xffffffffu, t, o);
    float mu = t * (1.f / 64.f);
    float d0 = v0 - mu, d1 = v1 - mu;
    float q = d0 * d0 + d1 * d1;
    #pragma unroll
    for (int o = 16; o > 0; o >>= 1) q += __shfl_xor_sync(0xffffffffu, q, o);
    float sc = rsqrtf(q * (1.f / 64.f) + EPS_IN);

    out[(size_t)n * 64 + l]      = d0 * sc;
    out[(size_t)n * 64 + l + 32] = d1 * sc;
}

// ---------------- launch ----------------
extern "C" void kernel_launch(void* const* d_in, const int* in_sizes, int n_in,
                              void* d_out, int out_size) {
    const float* x     = (const float*)d_in[0];
    const void*  ei    = d_in[1];
    const float* ea    = (const float*)d_in[2];
    const float* Wl1   = (const float*)d_in[3];
    const float* bl1   = (const float*)d_in[4];
    const float* Wr1   = (const float*)d_in[5];
    const float* br1   = (const float*)d_in[6];
    const float* We1   = (const float*)d_in[7];
    const float* att1  = (const float*)d_in[8];
    const float* bo1   = (const float*)d_in[9];
    const float* Wl2   = (const float*)d_in[10];
    const float* bl2   = (const float*)d_in[11];
    const float* Wr2   = (const float*)d_in[12];
    const float* br2   = (const float*)d_in[13];
    const float* We2   = (const float*)d_in[14];
    const float* att2  = (const float*)d_in[15];
    const float* bo2   = (const float*)d_in[16];
    const float* Wskip = (const float*)d_in[17];
    const float* bskip = (const float*)d_in[18];
    float* out = (float*)d_out;

    cudaFuncSetAttribute(lin_kernel,       cudaFuncAttributeMaxDynamicSharedMemorySize, SMEM_LIN);
    cudaFuncSetAttribute(score_mma_kernel, cudaFuncAttributeMaxDynamicSharedMemorySize, SMEM_SCORE);

    const int EB = (NEDGES + 255) / 256;
    const int NT = (NNODES + 127) / 128;
    const int ET = NEDGES / 128;

    // wdup slots: 0=Wl1 1=Wr1 2=Wskip 3=We1 4=Wl2 5=Wr2 6=We2
    prep_kernel<<<391, 256>>>((const int*)ei, Wl1, Wr1, Wskip, We1, Wl2, Wr2, We2);  // 1
    convert_count_kernel<<<EB, 256>>>(ei);                                            // 2
    scan_kernel<<<1, 1024>>>();                                                       // 3
    lin_kernel<<<NT, 256, SMEM_LIN>>>(x, 0, 3, 0, bl1, br1, bskip, NNODES);           // 4 (profiled)
    place_kernel<<<EB, 256>>>();                                                      // 5
    score_mma_kernel<<<ET, 128, SMEM_SCORE>>>(ea, 0, att1);                           // 6
    aggregate_kernel<<<(NNODES + 7) / 8, 256>>>(bo1, 0, nullptr);                     // 7
    lin_kernel<<<NT, 256, SMEM_LIN>>>(nullptr, 1, 2, 4, bl2, br2, nullptr, NNODES);   // 8
    score_mma_kernel<<<ET, 128, SMEM_SCORE>>>(ea, 1, att2);                           // 9
    aggregate_kernel<<<(NNODES + 7) / 8, 256>>>(bo2, 1, out);                         // 10
}

// round 7
// speedup vs baseline: 2.1908x; 1.1028x over previous
#include <cuda_runtime.h>
#include <cuda_bf16.h>
#include <cstdint>

#define NNODES 100000
#define NEDGES 1600000
#define NEG_SLOPE 0.2f
#define EPS_IN 1e-5f

typedef unsigned long long u64;

// ---------------- scratch ----------------
__device__ float g_xl[NNODES * 64];
__device__ float g_xr[NNODES * 64];
__device__ float g_h[NNODES * 64];
__device__ float g_skip[NNODES * 64];
__device__ float g_score[NEDGES];
__device__ int   g_esrc[NEDGES];
__device__ int   g_edsts[NEDGES];
__device__ int   g_eorig[NEDGES];
__device__ int   g_src[NEDGES];
__device__ int   g_dst[NEDGES];
__device__ int   g_deg[NNODES];
__device__ int   g_rowptr[NNODES + 1];
__device__ int   g_cursor[NNODES];
__device__ int   g_is64;
// 7 weight mats as hi/lo bf16 images: [slot][hi/lo][n=64][k padded to 72]
__device__ __nv_bfloat16 g_wb16[7 * 2 * 64 * 72];
#define WIMG_BYTES 18432

// ---------------- helpers ----------------
__device__ __forceinline__ uint32_t smem_u32(const void* p) {
    uint32_t a;
    asm("{ .reg .u64 t; cvta.to.shared.u64 t, %1; cvt.u32.u64 %0, t; }" : "=r"(a) : "l"(p));
    return a;
}

__device__ __forceinline__ void ldsm_x4(uint32_t& r0, uint32_t& r1, uint32_t& r2, uint32_t& r3,
                                        uint32_t addr) {
    asm volatile("ldmatrix.sync.aligned.m8n8.x4.shared.b16 {%0,%1,%2,%3}, [%4];"
                 : "=r"(r0), "=r"(r1), "=r"(r2), "=r"(r3) : "r"(addr));
}

__device__ __forceinline__ void mma_bf16(float& c0, float& c1, float& c2, float& c3,
                                         uint32_t a0, uint32_t a1, uint32_t a2, uint32_t a3,
                                         uint32_t b0, uint32_t b1) {
    asm volatile(
        "mma.sync.aligned.m16n8k16.row.col.f32.bf16.bf16.f32 "
        "{%0,%1,%2,%3}, {%4,%5,%6,%7}, {%8,%9}, {%0,%1,%2,%3};"
        : "+f"(c0), "+f"(c1), "+f"(c2), "+f"(c3)
        : "r"(a0), "r"(a1), "r"(a2), "r"(a3), "r"(b0), "r"(b1));
}

// split 8 consecutive floats into packed bf16 hi/lo uint4s
__device__ __forceinline__ void split8(const float* vv, uint4& hq, uint4& lq) {
    uint32_t hbits[4], lbits[4];
    #pragma unroll
    for (int j = 0; j < 4; j++) {
        __nv_bfloat16 h0 = __float2bfloat16_rn(vv[2 * j]);
        __nv_bfloat16 h1 = __float2bfloat16_rn(vv[2 * j + 1]);
        __nv_bfloat16 l0 = __float2bfloat16_rn(vv[2 * j]     - __bfloat162float(h0));
        __nv_bfloat16 l1 = __float2bfloat16_rn(vv[2 * j + 1] - __bfloat162float(h1));
        hbits[j] = (uint32_t)__bfloat16_as_ushort(h0) | ((uint32_t)__bfloat16_as_ushort(h1) << 16);
        lbits[j] = (uint32_t)__bfloat16_as_ushort(l0) | ((uint32_t)__bfloat16_as_ushort(l1) << 16);
    }
    hq = make_uint4(hbits[0], hbits[1], hbits[2], hbits[3]);
    lq = make_uint4(lbits[0], lbits[1], lbits[2], lbits[3]);
}

// 3-pass hi/lo MMA over staged A (144B rows) and B (144B rows) images.
// Warp covers rows wid*32..+31, all 64 cols.
__device__ __forceinline__ void mma3pass(uint32_t sb, int oAhi, int oAlo, int oBhi, int oBlo,
                                         int wid, int lane, float acc[2][8][4]) {
    #pragma unroll
    for (int pass = 0; pass < 3; pass++) {
        uint32_t Ab = sb + ((pass < 2) ? oAhi : oAlo);
        uint32_t Bb = sb + ((pass == 1) ? oBlo : oBhi);
        #pragma unroll
        for (int kb = 0; kb < 4; kb++) {
            uint32_t a[2][4];
            #pragma unroll
            for (int mi = 0; mi < 2; mi++) {
                int row = wid * 32 + mi * 16 + (lane & 15);
                int k = kb * 16 + ((lane & 16) ? 8 : 0);
                ldsm_x4(a[mi][0], a[mi][1], a[mi][2], a[mi][3], Ab + row * 144 + k * 2);
            }
            #pragma unroll
            for (int njp = 0; njp < 4; njp++) {
                int n = njp * 16 + ((lane & 16) ? 8 : 0) + (lane & 7);
                int k = kb * 16 + ((lane & 8) ? 8 : 0);
                uint32_t b0, b1, b2, b3;
                ldsm_x4(b0, b1, b2, b3, Bb + n * 144 + k * 2);
                #pragma unroll
                for (int mi = 0; mi < 2; mi++) {
                    mma_bf16(acc[mi][2 * njp][0], acc[mi][2 * njp][1],
                             acc[mi][2 * njp][2], acc[mi][2 * njp][3],
                             a[mi][0], a[mi][1], a[mi][2], a[mi][3], b0, b1);
                    mma_bf16(acc[mi][2 * njp + 1][0], acc[mi][2 * njp + 1][1],
                             acc[mi][2 * njp + 1][2], acc[mi][2 * njp + 1][3],
                             a[mi][0], a[mi][1], a[mi][2], a[mi][3], b2, b3);
                }
            }
        }
    }
}

// ---------------- launch 1: detect dtype + zero deg + build weight images ----------------
__global__ void prep_kernel(const int* w,
                            const float* W0, const float* W1, const float* W2,
                            const float* W3, const float* W4, const float* W5,
                            const float* W6)
{
    int bid = blockIdx.x, tid = threadIdx.x;
    if (bid == 0 && tid < 32) {
        int z = (w[2 * tid + 1] == 0) ? 1 : 0;
        unsigned b = __ballot_sync(0xffffffffu, z != 0);
        if (tid == 0) g_is64 = (b == 0xffffffffu) ? 1 : 0;
    }
    int i = bid * 256 + tid;
    if (i < NNODES) g_deg[i] = 0;
    if (i < 7 * 4096) {
        const float* Ws[7] = {W0, W1, W2, W3, W4, W5, W6};
        int slot = i >> 12, r = i & 4095;
        int n = r >> 6, k = r & 63;
        float v = Ws[slot][n * 64 + k];
        __nv_bfloat16 hi = __float2bfloat16_rn(v);
        __nv_bfloat16 lo = __float2bfloat16_rn(v - __bfloat162float(hi));
        g_wb16[((slot * 2 + 0) * 64 + n) * 72 + k] = hi;
        g_wb16[((slot * 2 + 1) * 64 + n) * 72 + k] = lo;
    }
}

// ---------------- launch 2: convert edge index + count ----------------
__global__ void convert_count_kernel(const void* ei) {
    int e = blockIdx.x * blockDim.x + threadIdx.x;
    if (e >= NEDGES) return;
    int s, d;
    if (g_is64) {
        const long long* p = (const long long*)ei;
        s = (int)p[e]; d = (int)p[NEDGES + e];
    } else {
        const int* p = (const int*)ei;
        s = p[e]; d = p[NEDGES + e];
    }
    g_src[e] = s; g_dst[e] = d;
    atomicAdd(&g_deg[d], 1);
}

__global__ void scan_kernel() {
    __shared__ int part[1024];
    int tid = threadIdx.x;
    const int chunk = (NNODES + 1023) / 1024;
    int start = tid * chunk;
    int end = start + chunk; if (end > NNODES) end = NNODES;
    int s = 0;
    for (int i = start; i < end; i++) s += g_deg[i];
    part[tid] = s;
    __syncthreads();
    for (int off = 1; off < 1024; off <<= 1) {
        int v = (tid >= off) ? part[tid - off] : 0;
        __syncthreads();
        part[tid] += v;
        __syncthreads();
    }
    int base = (tid == 0) ? 0 : part[tid - 1];
    for (int i = start; i < end; i++) {
        g_rowptr[i] = base;
        g_cursor[i] = base;
        base += g_deg[i];
    }
    if (tid == 1023) g_rowptr[NNODES] = base;
}

__global__ void place_kernel() {
    int e = blockIdx.x * blockDim.x + threadIdx.x;
    if (e >= NEDGES) return;
    int dst = g_dst[e];
    int pos = atomicAdd(&g_cursor[dst], 1);
    g_esrc[pos] = g_src[e];
    g_edsts[pos] = dst;
    g_eorig[pos] = e;
}

// ---------------- HMMA node linears: up to 3 weight sets over one A tile ----------------
// smem: A hi (18432) | A lo (18432) | B hi (9216) | B lo (9216) | bias (256)
#define L_AHI 0
#define L_ALO 18432
#define L_BHI 36864
#define L_BLO 46080
#define L_BIAS 55296
#define SMEM_LINM (55296 + 256)

__global__ void __launch_bounds__(128, 2) lin_mma_kernel(
    const float* Aext, int asel, int nsets, int slot0,
    const float* __restrict__ b0, const float* __restrict__ b1,
    const float* __restrict__ b2, int nrows)
{
    extern __shared__ __align__(16) char sm[];
    uint32_t sb = smem_u32(sm);
    float* s_bias = (float*)(sm + L_BIAS);

    const float* A = (asel == 1) ? g_h : Aext;
    int tid = threadIdx.x;
    int wid = tid >> 5, lane = tid & 31;
    int r0 = blockIdx.x * 128;

    // stage A hi/lo (clamp rows)
    #pragma unroll
    for (int i = 0; i < 8; i++) {
        int u = tid + (i << 7);
        int row = u >> 3, ch = u & 7;
        int rr = r0 + row;
        int srcrow = (rr < nrows) ? rr : 0;
        const float4* src = (const float4*)(A + (size_t)srcrow * 64 + ch * 8);
        float4 v0 = src[0], v1 = src[1];
        float vv[8] = {v0.x, v0.y, v0.z, v0.w, v1.x, v1.y, v1.z, v1.w};
        uint4 hq, lq; split8(vv, hq, lq);
        int off = row * 144 + ch * 16;
        *(uint4*)(sm + L_AHI + off) = hq;
        *(uint4*)(sm + L_ALO + off) = lq;
    }

    const float* bs[3] = {b0, b1, b2};
    float* outs[3] = {g_xl, g_xr, g_skip};

    for (int s = 0; s < nsets; s++) {
        __syncthreads();   // A ready (s==0) / previous set's ldsm+epilogue done
        {
            const uint4* wp = (const uint4*)((const char*)g_wb16 + (size_t)(slot0 + s) * WIMG_BYTES);
            uint4* bsm = (uint4*)(sm + L_BHI);
            #pragma unroll
            for (int i = 0; i < 9; i++) bsm[tid + 128 * i] = wp[tid + 128 * i];
            if (tid < 64) s_bias[tid] = bs[s][tid];
        }
        __syncthreads();

        float acc[2][8][4];
        #pragma unroll
        for (int mi = 0; mi < 2; mi++)
            #pragma unroll
            for (int nj = 0; nj < 8; nj++)
                #pragma unroll
                for (int c = 0; c < 4; c++) acc[mi][nj][c] = 0.f;

        mma3pass(sb, L_AHI, L_ALO, L_BHI, L_BLO, wid, lane, acc);

        // epilogue: add bias, write float2 pairs
        float* O = outs[s];
        int q = lane >> 2, r4 = lane & 3;
        #pragma unroll
        for (int mi = 0; mi < 2; mi++) {
            int rowA = r0 + wid * 32 + mi * 16 + q;
            #pragma unroll
            for (int nj = 0; nj < 8; nj++) {
                int n = nj * 8 + 2 * r4;
                float ba = s_bias[n], bb = s_bias[n + 1];
                if (rowA < nrows)
                    *(float2*)(O + (size_t)rowA * 64 + n) =
                        make_float2(acc[mi][nj][0] + ba, acc[mi][nj][1] + bb);
                if (rowA + 8 < nrows)
                    *(float2*)(O + (size_t)(rowA + 8) * 64 + n) =
                        make_float2(acc[mi][nj][2] + ba, acc[mi][nj][3] + bb);
            }
        }
    }
}

// ---------------- HMMA edge score ----------------
#define O_ORIG 0
#define O_ATT  512
#define O_MIN  768                        // 128 rows x 68 floats
#define O_AHI  (O_MIN + 128*68*4)         // 35584
#define O_ALO  (O_AHI + 18432)
#define O_BHI  (O_ALO + 18432)
#define O_BLO  (O_BHI + 9216)
#define SMEM_SCORE (O_BLO + 9216)         // 90880 B

__global__ void __launch_bounds__(128, 2) score_mma_kernel(
    const float* __restrict__ ea, int slot, const float* __restrict__ att)
{
    extern __shared__ __align__(16) char sm[];
    int*   s_orig = (int*)(sm + O_ORIG);
    float* s_att  = (float*)(sm + O_ATT);
    float* s_min  = (float*)(sm + O_MIN);
    uint32_t sb = smem_u32(sm);

    int tid = threadIdx.x;
    int wid = tid >> 5, lane = tid & 31;
    int r0 = blockIdx.x * 128;

    s_orig[tid] = g_eorig[r0 + tid];
    if (tid < 64) s_att[tid] = att[tid];

    {
        const uint4* wp = (const uint4*)((const char*)g_wb16 + (size_t)slot * WIMG_BYTES);
        uint4* bsm = (uint4*)(sm + O_BHI);
        #pragma unroll
        for (int i = 0; i < 9; i++) bsm[tid + 128 * i] = wp[tid + 128 * i];
    }
    __syncthreads();   // s_orig ready

    #pragma unroll
    for (int i = 0; i < 8; i++) {
        int u = tid + (i << 7);
        int row = u >> 3, ch = u & 7;
        int orig = s_orig[row];
        const float4* src = (const float4*)(ea + (size_t)orig * 64 + ch * 8);
        float4 v0 = src[0], v1 = src[1];
        float vv[8] = {v0.x, v0.y, v0.z, v0.w, v1.x, v1.y, v1.z, v1.w};
        uint4 hq, lq; split8(vv, hq, lq);
        int off = row * 144 + ch * 16;
        *(uint4*)(sm + O_AHI + off) = hq;
        *(uint4*)(sm + O_ALO + off) = lq;
    }

    #pragma unroll
    for (int i = 0; i < 16; i++) {
        int u = tid + (i << 7);
        int row = u >> 4, c4 = u & 15;
        int rr = r0 + row;
        int s = g_esrc[rr], d = g_edsts[rr];
        float4 a = *(const float4*)(g_xl + (size_t)s * 64 + c4 * 4);
        float4 b = *(const float4*)(g_xr + (size_t)d * 64 + c4 * 4);
        *(float4*)(s_min + row * 68 + c4 * 4) =
            make_float4(a.x + b.x, a.y + b.y, a.z + b.z, a.w + b.w);
    }
    __syncthreads();

    float acc[2][8][4];
    #pragma unroll
    for (int mi = 0; mi < 2; mi++)
        #pragma unroll
        for (int nj = 0; nj < 8; nj++)
            #pragma unroll
            for (int c = 0; c < 4; c++) acc[mi][nj][c] = 0.f;

    mma3pass(sb, O_AHI, O_ALO, O_BHI, O_BLO, wid, lane, acc);

    // epilogue: add m_init, leaky-relu, dot att, per-row reduce
    int q = lane >> 2, r4 = lane & 3;
    float psum[4] = {0.f, 0.f, 0.f, 0.f};
    #pragma unroll
    for (int mi = 0; mi < 2; mi++) {
        int rowA = wid * 32 + mi * 16 + q;
        #pragma unroll
        for (int nj = 0; nj < 8; nj++) {
            int n = nj * 8 + 2 * r4;
            float a0 = s_att[n], a1 = s_att[n + 1];
            float2 m0 = *(const float2*)(s_min + rowA * 68 + n);
            float2 m1 = *(const float2*)(s_min + (rowA + 8) * 68 + n);
            float v;
            v = acc[mi][nj][0] + m0.x; psum[2 * mi]     += fmaxf(v, NEG_SLOPE * v) * a0;
            v = acc[mi][nj][1] + m0.y; psum[2 * mi]     += fmaxf(v, NEG_SLOPE * v) * a1;
            v = acc[mi][nj][2] + m1.x; psum[2 * mi + 1] += fmaxf(v, NEG_SLOPE * v) * a0;
            v = acc[mi][nj][3] + m1.y; psum[2 * mi + 1] += fmaxf(v, NEG_SLOPE * v) * a1;
        }
    }
    #pragma unroll
    for (int j = 0; j < 4; j++) {
        psum[j] += __shfl_xor_sync(0xffffffffu, psum[j], 1);
        psum[j] += __shfl_xor_sync(0xffffffffu, psum[j], 2);
    }
    if (r4 == 0) {
        int base = r0 + wid * 32 + q;
        g_score[base]      = psum[0];
        g_score[base + 8]  = psum[1];
        g_score[base + 16] = psum[2];
        g_score[base + 24] = psum[3];
    }
}

// ---------------- per-node softmax + gather + relu + instnorm ----------------
__global__ void aggregate_kernel(const float* __restrict__ bo,
                                 int useskip, float* out_ext)
{
    __shared__ float s_a[8][32];
    __shared__ int   s_s[8][32];
    float* out = out_ext ? out_ext : g_h;
    int tid = threadIdx.x;
    int w = tid >> 5, l = tid & 31;
    int n = blockIdx.x * 8 + w;
    if (n >= NNODES) return;

    int r0 = g_rowptr[n], r1 = g_rowptr[n + 1];

    float mx = -3.402823466e38f;
    for (int i = r0 + l; i < r1; i += 32) mx = fmaxf(mx, g_score[i]);
    #pragma unroll
    for (int o = 16; o > 0; o >>= 1) mx = fmaxf(mx, __shfl_xor_sync(0xffffffffu, mx, o));

    float ss = 0.f;
    for (int i = r0 + l; i < r1; i += 32) ss += __expf(g_score[i] - mx);
    #pragma unroll
    for (int o = 16; o > 0; o >>= 1) ss += __shfl_xor_sync(0xffffffffu, ss, o);
    float inv = 1.f / (ss + 1e-16f);

    float acc0 = 0.f, acc1 = 0.f;
    for (int c = r0; c < r1; c += 32) {
        int i = c + l;
        if (i < r1) {
            s_a[w][l] = __expf(g_score[i] - mx) * inv;
            s_s[w][l] = g_esrc[i];
        }
        __syncwarp();
        int cnt = r1 - c; if (cnt > 32) cnt = 32;
        #pragma unroll 4
        for (int j = 0; j < cnt; j++) {
            float a = s_a[w][j];
            const float* xs = g_xl + (size_t)s_s[w][j] * 64;
            acc0 += a * __ldg(xs + l);
            acc1 += a * __ldg(xs + l + 32);
        }
        __syncwarp();
    }

    float v0 = acc0 + bo[l];
    float v1 = acc1 + bo[l + 32];
    if (useskip) {
        v0 += g_skip[(size_t)n * 64 + l];
        v1 += g_skip[(size_t)n * 64 + l + 32];
    }
    v0 = fmaxf(v0, 0.f);
    v1 = fmaxf(v1, 0.f);

    float t = v0 + v1;
    #pragma unroll
    for (int o = 16; o > 0; o >>= 1) t += __shfl_xor_sync(0xffffffffu, t, o);
    float mu = t * (1.f / 64.f);
    float d0 = v0 - mu, d1 = v1 - mu;
    float q = d0 * d0 + d1 * d1;
    #pragma unroll
    for (int o = 16; o > 0; o >>= 1) q += __shfl_xor_sync(0xffffffffu, q, o);
    float sc = rsqrtf(q * (1.f / 64.f) + EPS_IN);

    out[(size_t)n * 64 + l]      = d0 * sc;
    out[(size_t)n * 64 + l + 32] = d1 * sc;
}

// ---------------- launch ----------------
extern "C" void kernel_launch(void* const* d_in, const int* in_sizes, int n_in,
                              void* d_out, int out_size) {
    const float* x     = (const float*)d_in[0];
    const void*  ei    = d_in[1];
    const float* ea    = (const float*)d_in[2];
    const float* Wl1   = (const float*)d_in[3];
    const float* bl1   = (const float*)d_in[4];
    const float* Wr1   = (const float*)d_in[5];
    const float* br1   = (const float*)d_in[6];
    const float* We1   = (const float*)d_in[7];
    const float* att1  = (const float*)d_in[8];
    const float* bo1   = (const float*)d_in[9];
    const float* Wl2   = (const float*)d_in[10];
    const float* bl2   = (const float*)d_in[11];
    const float* Wr2   = (const float*)d_in[12];
    const float* br2   = (const float*)d_in[13];
    const float* We2   = (const float*)d_in[14];
    const float* att2  = (const float*)d_in[15];
    const float* bo2   = (const float*)d_in[16];
    const float* Wskip = (const float*)d_in[17];
    const float* bskip = (const float*)d_in[18];
    float* out = (float*)d_out;

    cudaFuncSetAttribute(lin_mma_kernel,   cudaFuncAttributeMaxDynamicSharedMemorySize, SMEM_LINM);
    cudaFuncSetAttribute(score_mma_kernel, cudaFuncAttributeMaxDynamicSharedMemorySize, SMEM_SCORE);

    const int EB = (NEDGES + 255) / 256;
    const int NT = (NNODES + 127) / 128;
    const int ET = NEDGES / 128;

    // weight slots: 0=Wl1 1=Wr1 2=Wskip 3=We1 4=Wl2 5=Wr2 6=We2
    prep_kernel<<<391, 256>>>((const int*)ei, Wl1, Wr1, Wskip, We1, Wl2, Wr2, We2);    // 1
    convert_count_kernel<<<EB, 256>>>(ei);                                              // 2
    scan_kernel<<<1, 1024>>>();                                                         // 3
    lin_mma_kernel<<<NT, 128, SMEM_LINM>>>(x, 0, 3, 0, bl1, br1, bskip, NNODES);        // 4 (profiled)
    place_kernel<<<EB, 256>>>();                                                        // 5
    score_mma_kernel<<<ET, 128, SMEM_SCORE>>>(ea, 3, att1);                             // 6
    aggregate_kernel<<<(NNODES + 7) / 8, 256>>>(bo1, 0, nullptr);                       // 7
    lin_mma_kernel<<<NT, 128, SMEM_LINM>>>(nullptr, 1, 2, 4, bl2, br2, nullptr, NNODES);// 8
    score_mma_kernel<<<ET, 128, SMEM_SCORE>>>(ea, 6, att2);                             // 9
    aggregate_kernel<<<(NNODES + 7) / 8, 256>>>(bo2, 1, out);                           // 10
}

// round 9
// speedup vs baseline: 2.3361x; 1.0663x over previous
#include <cuda_runtime.h>
#include <cuda_bf16.h>
#include <cstdint>

#define NNODES 100000
#define NEDGES 1600000
#define NEG_SLOPE 0.2f
#define EPS_IN 1e-5f

typedef unsigned long long u64;

// ---------------- scratch ----------------
__device__ float g_xl[NNODES * 64];
__device__ float g_xr[NNODES * 64];
__device__ float g_h[NNODES * 64];
__device__ float g_skip[NNODES * 64];
__device__ float g_score[NEDGES];
__device__ int   g_esrc[NEDGES];
__device__ int   g_edsts[NEDGES];
__device__ int   g_eorig[NEDGES];
__device__ int   g_src[NEDGES];
__device__ int   g_dst[NEDGES];
__device__ int   g_deg[NNODES];
__device__ int   g_rowptr[NNODES + 1];
__device__ int   g_cursor[NNODES];
__device__ int   g_is64;
// 7 weight mats as hi/lo bf16 images: [slot][hi/lo][n=64][k padded to 72]
__device__ __nv_bfloat16 g_wb16[7 * 2 * 64 * 72];
#define WIMG_BYTES 18432

// ---------------- helpers ----------------
__device__ __forceinline__ uint32_t smem_u32(const void* p) {
    uint32_t a;
    asm("{ .reg .u64 t; cvta.to.shared.u64 t, %1; cvt.u32.u64 %0, t; }" : "=r"(a) : "l"(p));
    return a;
}

__device__ __forceinline__ void ldsm_x4(uint32_t& r0, uint32_t& r1, uint32_t& r2, uint32_t& r3,
                                        uint32_t addr) {
    asm volatile("ldmatrix.sync.aligned.m8n8.x4.shared.b16 {%0,%1,%2,%3}, [%4];"
                 : "=r"(r0), "=r"(r1), "=r"(r2), "=r"(r3) : "r"(addr));
}

__device__ __forceinline__ void mma_bf16(float& c0, float& c1, float& c2, float& c3,
                                         uint32_t a0, uint32_t a1, uint32_t a2, uint32_t a3,
                                         uint32_t b0, uint32_t b1) {
    asm volatile(
        "mma.sync.aligned.m16n8k16.row.col.f32.bf16.bf16.f32 "
        "{%0,%1,%2,%3}, {%4,%5,%6,%7}, {%8,%9}, {%0,%1,%2,%3};"
        : "+f"(c0), "+f"(c1), "+f"(c2), "+f"(c3)
        : "r"(a0), "r"(a1), "r"(a2), "r"(a3), "r"(b0), "r"(b1));
}

// split 8 consecutive floats into packed bf16 hi/lo uint4s
__device__ __forceinline__ void split8(const float* vv, uint4& hq, uint4& lq) {
    uint32_t hbits[4], lbits[4];
    #pragma unroll
    for (int j = 0; j < 4; j++) {
        __nv_bfloat16 h0 = __float2bfloat16_rn(vv[2 * j]);
        __nv_bfloat16 h1 = __float2bfloat16_rn(vv[2 * j + 1]);
        __nv_bfloat16 l0 = __float2bfloat16_rn(vv[2 * j]     - __bfloat162float(h0));
        __nv_bfloat16 l1 = __float2bfloat16_rn(vv[2 * j + 1] - __bfloat162float(h1));
        hbits[j] = (uint32_t)__bfloat16_as_ushort(h0) | ((uint32_t)__bfloat16_as_ushort(h1) << 16);
        lbits[j] = (uint32_t)__bfloat16_as_ushort(l0) | ((uint32_t)__bfloat16_as_ushort(l1) << 16);
    }
    hq = make_uint4(hbits[0], hbits[1], hbits[2], hbits[3]);
    lq = make_uint4(lbits[0], lbits[1], lbits[2], lbits[3]);
}

// ---------------- launch 1: detect dtype + zero deg + build weight images ----------------
__global__ void prep_kernel(const int* w,
                            const float* W0, const float* W1, const float* W2,
                            const float* W3, const float* W4, const float* W5,
                            const float* W6)
{
    int bid = blockIdx.x, tid = threadIdx.x;
    if (bid == 0 && tid < 32) {
        int z = (w[2 * tid + 1] == 0) ? 1 : 0;
        unsigned b = __ballot_sync(0xffffffffu, z != 0);
        if (tid == 0) g_is64 = (b == 0xffffffffu) ? 1 : 0;
    }
    int i = bid * 256 + tid;
    if (i < NNODES) g_deg[i] = 0;
    if (i < 7 * 4096) {
        const float* Ws[7] = {W0, W1, W2, W3, W4, W5, W6};
        int slot = i >> 12, r = i & 4095;
        int n = r >> 6, k = r & 63;
        float v = Ws[slot][n * 64 + k];
        __nv_bfloat16 hi = __float2bfloat16_rn(v);
        __nv_bfloat16 lo = __float2bfloat16_rn(v - __bfloat162float(hi));
        g_wb16[((slot * 2 + 0) * 64 + n) * 72 + k] = hi;
        g_wb16[((slot * 2 + 1) * 64 + n) * 72 + k] = lo;
    }
}

// ---------------- launch 2: convert edge index + count ----------------
__global__ void convert_count_kernel(const void* ei) {
    int e = blockIdx.x * blockDim.x + threadIdx.x;
    if (e >= NEDGES) return;
    int s, d;
    if (g_is64) {
        const long long* p = (const long long*)ei;
        s = (int)p[e]; d = (int)p[NEDGES + e];
    } else {
        const int* p = (const int*)ei;
        s = p[e]; d = p[NEDGES + e];
    }
    g_src[e] = s; g_dst[e] = d;
    atomicAdd(&g_deg[d], 1);
}

__global__ void scan_kernel() {
    __shared__ int part[1024];
    int tid = threadIdx.x;
    const int chunk = (NNODES + 1023) / 1024;
    int start = tid * chunk;
    int end = start + chunk; if (end > NNODES) end = NNODES;
    int s = 0;
    for (int i = start; i < end; i++) s += g_deg[i];
    part[tid] = s;
    __syncthreads();
    for (int off = 1; off < 1024; off <<= 1) {
        int v = (tid >= off) ? part[tid - off] : 0;
        __syncthreads();
        part[tid] += v;
        __syncthreads();
    }
    int base = (tid == 0) ? 0 : part[tid - 1];
    for (int i = start; i < end; i++) {
        g_rowptr[i] = base;
        g_cursor[i] = base;
        base += g_deg[i];
    }
    if (tid == 1023) g_rowptr[NNODES] = base;
}

__global__ void place_kernel() {
    int e = blockIdx.x * blockDim.x + threadIdx.x;
    if (e >= NEDGES) return;
    int dst = g_dst[e];
    int pos = atomicAdd(&g_cursor[dst], 1);
    g_esrc[pos] = g_src[e];
    g_edsts[pos] = dst;
    g_eorig[pos] = e;
}

// ---------------- HMMA node linears: up to 3 weight sets over one A tile ----------------
#define L_AHI 0
#define L_ALO 18432
#define L_BHI 36864
#define L_BLO 46080
#define L_BIAS 55296
#define SMEM_LINM (55296 + 256)

__global__ void __launch_bounds__(128, 2) lin_mma_kernel(
    const float* Aext, int asel, int nsets, int slot0,
    const float* __restrict__ b0, const float* __restrict__ b1,
    const float* __restrict__ b2, int nrows)
{
    extern __shared__ __align__(16) char sm[];
    uint32_t sb = smem_u32(sm);
    float* s_bias = (float*)(sm + L_BIAS);

    const float* A = (asel == 1) ? g_h : Aext;
    int tid = threadIdx.x;
    int wid = tid >> 5, lane = tid & 31;
    int r0 = blockIdx.x * 128;

    #pragma unroll
    for (int i = 0; i < 8; i++) {
        int u = tid + (i << 7);
        int row = u >> 3, ch = u & 7;
        int rr = r0 + row;
        int srcrow = (rr < nrows) ? rr : 0;
        const float4* src = (const float4*)(A + (size_t)srcrow * 64 + ch * 8);
        float4 v0 = src[0], v1 = src[1];
        float vv[8] = {v0.x, v0.y, v0.z, v0.w, v1.x, v1.y, v1.z, v1.w};
        uint4 hq, lq; split8(vv, hq, lq);
        int off = row * 144 + ch * 16;
        *(uint4*)(sm + L_AHI + off) = hq;
        *(uint4*)(sm + L_ALO + off) = lq;
    }

    const float* bs[3] = {b0, b1, b2};
    float* outs[3] = {g_xl, g_xr, g_skip};

    for (int s = 0; s < nsets; s++) {
        __syncthreads();
        {
            const uint4* wp = (const uint4*)((const char*)g_wb16 + (size_t)(slot0 + s) * WIMG_BYTES);
            uint4* bsm = (uint4*)(sm + L_BHI);
            #pragma unroll
            for (int i = 0; i < 9; i++) bsm[tid + 128 * i] = wp[tid + 128 * i];
            if (tid < 64) s_bias[tid] = bs[s][tid];
        }
        __syncthreads();

        float acc[2][8][4];
        #pragma unroll
        for (int mi = 0; mi < 2; mi++)
            #pragma unroll
            for (int nj = 0; nj < 8; nj++)
                #pragma unroll
                for (int c = 0; c < 4; c++) acc[mi][nj][c] = 0.f;

        #pragma unroll
        for (int pass = 0; pass < 3; pass++) {
            uint32_t Ab = sb + ((pass < 2) ? L_AHI : L_ALO);
            uint32_t Bb = sb + ((pass == 1) ? L_BLO : L_BHI);
            #pragma unroll
            for (int kb = 0; kb < 4; kb++) {
                uint32_t a[2][4];
                #pragma unroll
                for (int mi = 0; mi < 2; mi++) {
                    int row = wid * 32 + mi * 16 + (lane & 15);
                    int k = kb * 16 + ((lane & 16) ? 8 : 0);
                    ldsm_x4(a[mi][0], a[mi][1], a[mi][2], a[mi][3], Ab + row * 144 + k * 2);
                }
                #pragma unroll
                for (int njp = 0; njp < 4; njp++) {
                    int n = njp * 16 + ((lane & 16) ? 8 : 0) + (lane & 7);
                    int k = kb * 16 + ((lane & 8) ? 8 : 0);
                    uint32_t b0r, b1r, b2r, b3r;
                    ldsm_x4(b0r, b1r, b2r, b3r, Bb + n * 144 + k * 2);
                    #pragma unroll
                    for (int mi = 0; mi < 2; mi++) {
                        mma_bf16(acc[mi][2 * njp][0], acc[mi][2 * njp][1],
                                 acc[mi][2 * njp][2], acc[mi][2 * njp][3],
                                 a[mi][0], a[mi][1], a[mi][2], a[mi][3], b0r, b1r);
                        mma_bf16(acc[mi][2 * njp + 1][0], acc[mi][2 * njp + 1][1],
                                 acc[mi][2 * njp + 1][2], acc[mi][2 * njp + 1][3],
                                 a[mi][0], a[mi][1], a[mi][2], a[mi][3], b2r, b3r);
                    }
                }
            }
        }

        float* O = outs[s];
        int q = lane >> 2, r4 = lane & 3;
        #pragma unroll
        for (int mi = 0; mi < 2; mi++) {
            int rowA = r0 + wid * 32 + mi * 16 + q;
            #pragma unroll
            for (int nj = 0; nj < 8; nj++) {
                int n = nj * 8 + 2 * r4;
                float ba = s_bias[n], bb = s_bias[n + 1];
                if (rowA < nrows)
                    *(float2*)(O + (size_t)rowA * 64 + n) =
                        make_float2(acc[mi][nj][0] + ba, acc[mi][nj][1] + bb);
                if (rowA + 8 < nrows)
                    *(float2*)(O + (size_t)(rowA + 8) * 64 + n) =
                        make_float2(acc[mi][nj][2] + ba, acc[mi][nj][3] + bb);
            }
        }
    }
}

// ---------------- HMMA edge score: M=256 tile, 512 threads, 16 rows/warp ----------------
#define S_ORIG 0
#define S_SRC  1024
#define S_DST  2048
#define S_ATT  3072
#define S_AHI  3328
#define S_ALO  (S_AHI + 36864)
#define S_BHI  (S_ALO + 36864)
#define S_BLO  (S_BHI + 9216)
#define SMEM_SCORE (S_BLO + 9216)   // 95488

__global__ void __launch_bounds__(512, 1) score_mma_kernel(
    const float* __restrict__ ea, int slot, const float* __restrict__ att)
{
    extern __shared__ __align__(16) char sm[];
    int*   s_orig = (int*)(sm + S_ORIG);
    int*   s_src  = (int*)(sm + S_SRC);
    int*   s_dst  = (int*)(sm + S_DST);
    float* s_att  = (float*)(sm + S_ATT);
    uint32_t sb = smem_u32(sm);

    int tid = threadIdx.x;
    int wid = tid >> 5, lane = tid & 31;
    int r0 = blockIdx.x * 256;

    if (tid < 256) {
        s_orig[tid] = g_eorig[r0 + tid];
        s_src[tid]  = g_esrc[r0 + tid];
        s_dst[tid]  = g_edsts[r0 + tid];
    }
    if (tid < 64) s_att[tid] = att[tid];

    // stage B image (hi+lo): 18432B = 1152 uint4
    {
        const uint4* wp = (const uint4*)((const char*)g_wb16 + (size_t)slot * WIMG_BYTES);
        uint4* bsm = (uint4*)(sm + S_BHI);
        #pragma unroll
        for (int i = tid; i < 1152; i += 512) bsm[i] = wp[i];
    }
    __syncthreads();   // s_orig ready

    // stage A (256 gathered edge_attr rows, hi/lo split)
    #pragma unroll
    for (int i = 0; i < 4; i++) {
        int u = tid + (i << 9);
        int row = u >> 3, ch = u & 7;
        int orig = s_orig[row];
        const float4* src = (const float4*)(ea + (size_t)orig * 64 + ch * 8);
        float4 v0 = src[0], v1 = src[1];
        float vv[8] = {v0.x, v0.y, v0.z, v0.w, v1.x, v1.y, v1.z, v1.w};
        uint4 hq, lq; split8(vv, hq, lq);
        int off = row * 144 + ch * 16;
        *(uint4*)(sm + S_AHI + off) = hq;
        *(uint4*)(sm + S_ALO + off) = lq;
    }
    __syncthreads();

    float acc[8][4];
    #pragma unroll
    for (int nj = 0; nj < 8; nj++)
        #pragma unroll
        for (int c = 0; c < 4; c++) acc[nj][c] = 0.f;

    #pragma unroll
    for (int pass = 0; pass < 3; pass++) {
        uint32_t Ab = sb + ((pass < 2) ? S_AHI : S_ALO);
        uint32_t Bb = sb + ((pass == 1) ? S_BLO : S_BHI);
        #pragma unroll
        for (int kb = 0; kb < 4; kb++) {
            uint32_t a0, a1, a2, a3;
            {
                int row = wid * 16 + (lane & 15);
                int k = kb * 16 + ((lane & 16) ? 8 : 0);
                ldsm_x4(a0, a1, a2, a3, Ab + row * 144 + k * 2);
            }
            #pragma unroll
            for (int njp = 0; njp < 4; njp++) {
                int n = njp * 16 + ((lane & 16) ? 8 : 0) + (lane & 7);
                int k = kb * 16 + ((lane & 8) ? 8 : 0);
                uint32_t b0r, b1r, b2r, b3r;
                ldsm_x4(b0r, b1r, b2r, b3r, Bb + n * 144 + k * 2);
                mma_bf16(acc[2 * njp][0], acc[2 * njp][1], acc[2 * njp][2], acc[2 * njp][3],
                         a0, a1, a2, a3, b0r, b1r);
                mma_bf16(acc[2 * njp + 1][0], acc[2 * njp + 1][1], acc[2 * njp + 1][2], acc[2 * njp + 1][3],
                         a0, a1, a2, a3, b2r, b3r);
            }
        }
    }

    // epilogue: direct L2 gather of xl[src]+xr[dst], leaky-relu, dot att, reduce
    int q = lane >> 2, r4 = lane & 3;
    int rowA = wid * 16 + q;
    int sA = s_src[rowA],     dA = s_dst[rowA];
    int sB = s_src[rowA + 8], dB = s_dst[rowA + 8];
    const float* xlA = g_xl + (size_t)sA * 64;
    const float* xrA = g_xr + (size_t)dA * 64;
    const float* xlB = g_xl + (size_t)sB * 64;
    const float* xrB = g_xr + (size_t)dB * 64;

    float p0 = 0.f, p1 = 0.f;
    #pragma unroll
    for (int nj = 0; nj < 8; nj++) {
        int n = nj * 8 + 2 * r4;
        float a0 = s_att[n], a1 = s_att[n + 1];
        float2 la = *(const float2*)(xlA + n);
        float2 ra = *(const float2*)(xrA + n);
        float2 lb = *(const float2*)(xlB + n);
        float2 rb = *(const float2*)(xrB + n);
        float v;
        v = acc[nj][0] + la.x + ra.x; p0 += fmaxf(v, NEG_SLOPE * v) * a0;
        v = acc[nj][1] + la.y + ra.y; p0 += fmaxf(v, NEG_SLOPE * v) * a1;
        v = acc[nj][2] + lb.x + rb.x; p1 += fmaxf(v, NEG_SLOPE * v) * a0;
        v = acc[nj][3] + lb.y + rb.y; p1 += fmaxf(v, NEG_SLOPE * v) * a1;
    }
    p0 += __shfl_xor_sync(0xffffffffu, p0, 1);
    p0 += __shfl_xor_sync(0xffffffffu, p0, 2);
    p1 += __shfl_xor_sync(0xffffffffu, p1, 1);
    p1 += __shfl_xor_sync(0xffffffffu, p1, 2);
    if (r4 == 0) {
        g_score[r0 + rowA]     = p0;
        g_score[r0 + rowA + 8] = p1;
    }
}

// ---------------- per-node softmax + gather + relu + instnorm (float2 lanes) ----------------
__global__ void aggregate_kernel(const float* __restrict__ bo,
                                 int useskip, float* out_ext)
{
    __shared__ float s_a[8][32];
    __shared__ int   s_s[8][32];
    float* out = out_ext ? out_ext : g_h;
    int tid = threadIdx.x;
    int w = tid >> 5, l = tid & 31;
    int n = blockIdx.x * 8 + w;
    if (n >= NNODES) return;

    int r0 = g_rowptr[n], r1 = g_rowptr[n + 1];

    float mx = -3.402823466e38f;
    for (int i = r0 + l; i < r1; i += 32) mx = fmaxf(mx, g_score[i]);
    #pragma unroll
    for (int o = 16; o > 0; o >>= 1) mx = fmaxf(mx, __shfl_xor_sync(0xffffffffu, mx, o));

    float ss = 0.f;
    for (int i = r0 + l; i < r1; i += 32) ss += __expf(g_score[i] - mx);
    #pragma unroll
    for (int o = 16; o > 0; o >>= 1) ss += __shfl_xor_sync(0xffffffffu, ss, o);
    float inv = 1.f / (ss + 1e-16f);

    float acc0 = 0.f, acc1 = 0.f;   // cols 2l, 2l+1
    for (int c = r0; c < r1; c += 32) {
        int i = c + l;
        if (i < r1) {
            s_a[w][l] = __expf(g_score[i] - mx) * inv;
            s_s[w][l] = g_esrc[i];
        }
        __syncwarp();
        int cnt = r1 - c; if (cnt > 32) cnt = 32;
        #pragma unroll 4
        for (int j = 0; j < cnt; j++) {
            float a = s_a[w][j];
            float2 xv = __ldg((const float2*)(g_xl + (size_t)s_s[w][j] * 64) + l);
            acc0 += a * xv.x;
            acc1 += a * xv.y;
        }
        __syncwarp();
    }

    float2 bv = ((const float2*)bo)[l];
    float v0 = acc0 + bv.x;
    float v1 = acc1 + bv.y;
    if (useskip) {
        float2 sv = ((const float2*)(g_skip + (size_t)n * 64))[l];
        v0 += sv.x;
        v1 += sv.y;
    }
    v0 = fmaxf(v0, 0.f);
    v1 = fmaxf(v1, 0.f);

    float t = v0 + v1;
    #pragma unroll
    for (int o = 16; o > 0; o >>= 1) t += __shfl_xor_sync(0xffffffffu, t, o);
    float mu = t * (1.f / 64.f);
    float d0 = v0 - mu, d1 = v1 - mu;
    float q = d0 * d0 + d1 * d1;
    #pragma unroll
    for (int o = 16; o > 0; o >>= 1) q += __shfl_xor_sync(0xffffffffu, q, o);
    float sc = rsqrtf(q * (1.f / 64.f) + EPS_IN);

    ((float2*)(out + (size_t)n * 64))[l] = make_float2(d0 * sc, d1 * sc);
}

// ---------------- launch ----------------
extern "C" void kernel_launch(void* const* d_in, const int* in_sizes, int n_in,
                              void* d_out, int out_size) {
    const float* x     = (const float*)d_in[0];
    const void*  ei    = d_in[1];
    const float* ea    = (const float*)d_in[2];
    const float* Wl1   = (const float*)d_in[3];
    const float* bl1   = (const float*)d_in[4];
    const float* Wr1   = (const float*)d_in[5];
    const float* br1   = (const float*)d_in[6];
    const float* We1   = (const float*)d_in[7];
    const float* att1  = (const float*)d_in[8];
    const float* bo1   = (const float*)d_in[9];
    const float* Wl2   = (const float*)d_in[10];
    const float* bl2   = (const float*)d_in[11];
    const float* Wr2   = (const float*)d_in[12];
    const float* br2   = (const float*)d_in[13];
    const float* We2   = (const float*)d_in[14];
    const float* att2  = (const float*)d_in[15];
    const float* bo2   = (const float*)d_in[16];
    const float* Wskip = (const float*)d_in[17];
    const float* bskip = (const float*)d_in[18];
    float* out = (float*)d_out;

    cudaFuncSetAttribute(lin_mma_kernel,   cudaFuncAttributeMaxDynamicSharedMemorySize, SMEM_LINM);
    cudaFuncSetAttribute(score_mma_kernel, cudaFuncAttributeMaxDynamicSharedMemorySize, SMEM_SCORE);

    const int EB = (NEDGES + 255) / 256;
    const int NT = (NNODES + 127) / 128;
    const int ET = NEDGES / 256;   // 6250, exact

    // weight slots: 0=Wl1 1=Wr1 2=Wskip 3=We1 4=Wl2 5=Wr2 6=We2
    prep_kernel<<<391, 256>>>((const int*)ei, Wl1, Wr1, Wskip, We1, Wl2, Wr2, We2);    // 1
    convert_count_kernel<<<EB, 256>>>(ei);                                              // 2
    scan_kernel<<<1, 1024>>>();                                                         // 3
    lin_mma_kernel<<<NT, 128, SMEM_LINM>>>(x, 0, 3, 0, bl1, br1, bskip, NNODES);        // 4 (profiled)
    place_kernel<<<EB, 256>>>();                                                        // 5
    score_mma_kernel<<<ET, 512, SMEM_SCORE>>>(ea, 3, att1);                             // 6
    aggregate_kernel<<<(NNODES + 7) / 8, 256>>>(bo1, 0, nullptr);                       // 7
    lin_mma_kernel<<<NT, 128, SMEM_LINM>>>(nullptr, 1, 2, 4, bl2, br2, nullptr, NNODES);// 8
    score_mma_kernel<<<ET, 512, SMEM_SCORE>>>(ea, 6, att2);                             // 9
    aggregate_kernel<<<(NNODES + 7) / 8, 256>>>(bo2, 1, out);                           // 10
}

// round 10
// speedup vs baseline: 2.3628x; 1.0114x over previous
#include <cuda_runtime.h>
#include <cuda_bf16.h>
#include <cstdint>

#define NNODES 100000
#define NEDGES 1600000
#define NEG_SLOPE 0.2f
#define EPS_IN 1e-5f

typedef unsigned long long u64;

// ---------------- scratch ----------------
__device__ float g_xl[NNODES * 64];
__device__ float g_xr[NNODES * 64];
__device__ float g_h[NNODES * 64];
__device__ float g_skip[NNODES * 64];
__device__ float g_score[NEDGES];
__device__ int2  g_edge[NEDGES];    // (src,dst) at sorted pos
__device__ int   g_eorig[NEDGES];   // sorted pos -> original edge id
__device__ int2  g_ed0[NEDGES];     // (src,dst) original order
__device__ int   g_deg[NNODES];
__device__ int   g_rowptr[NNODES + 1];
__device__ int   g_cursor[NNODES];
__device__ int   g_is64;
// 7 weight mats as hi/lo bf16 images: [slot][hi/lo][n=64][k padded to 72]
__device__ __nv_bfloat16 g_wb16[7 * 2 * 64 * 72];
#define WIMG_BYTES 18432

// ---------------- helpers ----------------
__device__ __forceinline__ uint32_t smem_u32(const void* p) {
    uint32_t a;
    asm("{ .reg .u64 t; cvta.to.shared.u64 t, %1; cvt.u32.u64 %0, t; }" : "=r"(a) : "l"(p));
    return a;
}

__device__ __forceinline__ void ldsm_x4(uint32_t& r0, uint32_t& r1, uint32_t& r2, uint32_t& r3,
                                        uint32_t addr) {
    asm volatile("ldmatrix.sync.aligned.m8n8.x4.shared.b16 {%0,%1,%2,%3}, [%4];"
                 : "=r"(r0), "=r"(r1), "=r"(r2), "=r"(r3) : "r"(addr));
}

__device__ __forceinline__ void mma_bf16(float& c0, float& c1, float& c2, float& c3,
                                         uint32_t a0, uint32_t a1, uint32_t a2, uint32_t a3,
                                         uint32_t b0, uint32_t b1) {
    asm volatile(
        "mma.sync.aligned.m16n8k16.row.col.f32.bf16.bf16.f32 "
        "{%0,%1,%2,%3}, {%4,%5,%6,%7}, {%8,%9}, {%0,%1,%2,%3};"
        : "+f"(c0), "+f"(c1), "+f"(c2), "+f"(c3)
        : "r"(a0), "r"(a1), "r"(a2), "r"(a3), "r"(b0), "r"(b1));
}

__device__ __forceinline__ void split8(const float* vv, uint4& hq, uint4& lq) {
    uint32_t hbits[4], lbits[4];
    #pragma unroll
    for (int j = 0; j < 4; j++) {
        __nv_bfloat16 h0 = __float2bfloat16_rn(vv[2 * j]);
        __nv_bfloat16 h1 = __float2bfloat16_rn(vv[2 * j + 1]);
        __nv_bfloat16 l0 = __float2bfloat16_rn(vv[2 * j]     - __bfloat162float(h0));
        __nv_bfloat16 l1 = __float2bfloat16_rn(vv[2 * j + 1] - __bfloat162float(h1));
        hbits[j] = (uint32_t)__bfloat16_as_ushort(h0) | ((uint32_t)__bfloat16_as_ushort(h1) << 16);
        lbits[j] = (uint32_t)__bfloat16_as_ushort(l0) | ((uint32_t)__bfloat16_as_ushort(l1) << 16);
    }
    hq = make_uint4(hbits[0], hbits[1], hbits[2], hbits[3]);
    lq = make_uint4(lbits[0], lbits[1], lbits[2], lbits[3]);
}

// ---------------- launch 1: detect dtype + zero deg + build weight images ----------------
__global__ void prep_kernel(const int* w,
                            const float* W0, const float* W1, const float* W2,
                            const float* W3, const float* W4, const float* W5,
                            const float* W6)
{
    int bid = blockIdx.x, tid = threadIdx.x;
    if (bid == 0 && tid < 32) {
        int z = (w[2 * tid + 1] == 0) ? 1 : 0;
        unsigned b = __ballot_sync(0xffffffffu, z != 0);
        if (tid == 0) g_is64 = (b == 0xffffffffu) ? 1 : 0;
    }
    int i = bid * 256 + tid;
    if (i < NNODES) g_deg[i] = 0;
    if (i < 7 * 4096) {
        const float* Ws[7] = {W0, W1, W2, W3, W4, W5, W6};
        int slot = i >> 12, r = i & 4095;
        int n = r >> 6, k = r & 63;
        float v = Ws[slot][n * 64 + k];
        __nv_bfloat16 hi = __float2bfloat16_rn(v);
        __nv_bfloat16 lo = __float2bfloat16_rn(v - __bfloat162float(hi));
        g_wb16[((slot * 2 + 0) * 64 + n) * 72 + k] = hi;
        g_wb16[((slot * 2 + 1) * 64 + n) * 72 + k] = lo;
    }
}

// ---------------- launch 2: convert edge index + count ----------------
__global__ void convert_count_kernel(const void* ei) {
    int e = blockIdx.x * blockDim.x + threadIdx.x;
    if (e >= NEDGES) return;
    int s, d;
    if (g_is64) {
        const long long* p = (const long long*)ei;
        s = (int)p[e]; d = (int)p[NEDGES + e];
    } else {
        const int* p = (const int*)ei;
        s = p[e]; d = p[NEDGES + e];
    }
    g_ed0[e] = make_int2(s, d);
    atomicAdd(&g_deg[d], 1);
}

__global__ void scan_kernel() {
    __shared__ int part[1024];
    int tid = threadIdx.x;
    const int chunk = (NNODES + 1023) / 1024;
    int start = tid * chunk;
    int end = start + chunk; if (end > NNODES) end = NNODES;
    int s = 0;
    for (int i = start; i < end; i++) s += g_deg[i];
    part[tid] = s;
    __syncthreads();
    for (int off = 1; off < 1024; off <<= 1) {
        int v = (tid >= off) ? part[tid - off] : 0;
        __syncthreads();
        part[tid] += v;
        __syncthreads();
    }
    int base = (tid == 0) ? 0 : part[tid - 1];
    for (int i = start; i < end; i++) {
        g_rowptr[i] = base;
        g_cursor[i] = base;
        base += g_deg[i];
    }
    if (tid == 1023) g_rowptr[NNODES] = base;
}

__global__ void place_kernel() {
    int e = blockIdx.x * blockDim.x + threadIdx.x;
    if (e >= NEDGES) return;
    int2 sd = g_ed0[e];
    int pos = atomicAdd(&g_cursor[sd.y], 1);
    g_edge[pos] = sd;
    g_eorig[pos] = e;
}

// ---------------- HMMA node linears: up to 3 weight sets over one A tile ----------------
#define L_AHI 0
#define L_ALO 18432
#define L_BHI 36864
#define L_BLO 46080
#define L_BIAS 55296
#define SMEM_LINM (55296 + 256)

__global__ void __launch_bounds__(128, 2) lin_mma_kernel(
    const float* Aext, int asel, int nsets, int slot0,
    const float* __restrict__ b0, const float* __restrict__ b1,
    const float* __restrict__ b2, int nrows)
{
    extern __shared__ __align__(16) char sm[];
    uint32_t sb = smem_u32(sm);
    float* s_bias = (float*)(sm + L_BIAS);

    const float* A = (asel == 1) ? g_h : Aext;
    int tid = threadIdx.x;
    int wid = tid >> 5, lane = tid & 31;
    int r0 = blockIdx.x * 128;

    #pragma unroll
    for (int i = 0; i < 8; i++) {
        int u = tid + (i << 7);
        int row = u >> 3, ch = u & 7;
        int rr = r0 + row;
        int srcrow = (rr < nrows) ? rr : 0;
        const float4* src = (const float4*)(A + (size_t)srcrow * 64 + ch * 8);
        float4 v0 = src[0], v1 = src[1];
        float vv[8] = {v0.x, v0.y, v0.z, v0.w, v1.x, v1.y, v1.z, v1.w};
        uint4 hq, lq; split8(vv, hq, lq);
        int off = row * 144 + ch * 16;
        *(uint4*)(sm + L_AHI + off) = hq;
        *(uint4*)(sm + L_ALO + off) = lq;
    }

    const float* bs[3] = {b0, b1, b2};
    float* outs[3] = {g_xl, g_xr, g_skip};

    for (int s = 0; s < nsets; s++) {
        __syncthreads();
        {
            const uint4* wp = (const uint4*)((const char*)g_wb16 + (size_t)(slot0 + s) * WIMG_BYTES);
            uint4* bsm = (uint4*)(sm + L_BHI);
            #pragma unroll
            for (int i = 0; i < 9; i++) bsm[tid + 128 * i] = wp[tid + 128 * i];
            if (tid < 64) s_bias[tid] = bs[s][tid];
        }
        __syncthreads();

        float acc[2][8][4];
        #pragma unroll
        for (int mi = 0; mi < 2; mi++)
            #pragma unroll
            for (int nj = 0; nj < 8; nj++)
                #pragma unroll
                for (int c = 0; c < 4; c++) acc[mi][nj][c] = 0.f;

        #pragma unroll
        for (int pass = 0; pass < 3; pass++) {
            uint32_t Ab = sb + ((pass < 2) ? L_AHI : L_ALO);
            uint32_t Bb = sb + ((pass == 1) ? L_BLO : L_BHI);
            #pragma unroll
            for (int kb = 0; kb < 4; kb++) {
                uint32_t a[2][4];
                #pragma unroll
                for (int mi = 0; mi < 2; mi++) {
                    int row = wid * 32 + mi * 16 + (lane & 15);
                    int k = kb * 16 + ((lane & 16) ? 8 : 0);
                    ldsm_x4(a[mi][0], a[mi][1], a[mi][2], a[mi][3], Ab + row * 144 + k * 2);
                }
                #pragma unroll
                for (int njp = 0; njp < 4; njp++) {
                    int n = njp * 16 + ((lane & 16) ? 8 : 0) + (lane & 7);
                    int k = kb * 16 + ((lane & 8) ? 8 : 0);
                    uint32_t b0r, b1r, b2r, b3r;
                    ldsm_x4(b0r, b1r, b2r, b3r, Bb + n * 144 + k * 2);
                    #pragma unroll
                    for (int mi = 0; mi < 2; mi++) {
                        mma_bf16(acc[mi][2 * njp][0], acc[mi][2 * njp][1],
                                 acc[mi][2 * njp][2], acc[mi][2 * njp][3],
                                 a[mi][0], a[mi][1], a[mi][2], a[mi][3], b0r, b1r);
                        mma_bf16(acc[mi][2 * njp + 1][0], acc[mi][2 * njp + 1][1],
                                 acc[mi][2 * njp + 1][2], acc[mi][2 * njp + 1][3],
                                 a[mi][0], a[mi][1], a[mi][2], a[mi][3], b2r, b3r);
                    }
                }
            }
        }

        float* O = outs[s];
        int q = lane >> 2, r4 = lane & 3;
        #pragma unroll
        for (int mi = 0; mi < 2; mi++) {
            int rowA = r0 + wid * 32 + mi * 16 + q;
            #pragma unroll
            for (int nj = 0; nj < 8; nj++) {
                int n = nj * 8 + 2 * r4;
                float ba = s_bias[n], bb = s_bias[n + 1];
                if (rowA < nrows)
                    *(float2*)(O + (size_t)rowA * 64 + n) =
                        make_float2(acc[mi][nj][0] + ba, acc[mi][nj][1] + bb);
                if (rowA + 8 < nrows)
                    *(float2*)(O + (size_t)(rowA + 8) * 64 + n) =
                        make_float2(acc[mi][nj][2] + ba, acc[mi][nj][3] + bb);
            }
        }
    }
}

// ---------------- HMMA edge score: M=256 tile, 512 threads, 16 rows/warp ----------------
#define S_ORIG 0
#define S_EDGE 1024      // int2[256]
#define S_ATT  3072
#define S_AHI  3328
#define S_ALO  (S_AHI + 36864)
#define S_BHI  (S_ALO + 36864)
#define S_BLO  (S_BHI + 9216)
#define SMEM_SCORE (S_BLO + 9216)   // 95488

__global__ void __launch_bounds__(512, 1) score_mma_kernel(
    const float* __restrict__ ea, int slot, const float* __restrict__ att)
{
    extern __shared__ __align__(16) char sm[];
    int*   s_orig = (int*)(sm + S_ORIG);
    int2*  s_edge = (int2*)(sm + S_EDGE);
    float* s_att  = (float*)(sm + S_ATT);
    uint32_t sb = smem_u32(sm);

    int tid = threadIdx.x;
    int wid = tid >> 5, lane = tid & 31;
    int r0 = blockIdx.x * 256;

    if (tid < 256) {
        s_orig[tid] = g_eorig[r0 + tid];
        s_edge[tid] = g_edge[r0 + tid];
    }
    if (tid < 64) s_att[tid] = att[tid];

    {
        const uint4* wp = (const uint4*)((const char*)g_wb16 + (size_t)slot * WIMG_BYTES);
        uint4* bsm = (uint4*)(sm + S_BHI);
        #pragma unroll
        for (int i = tid; i < 1152; i += 512) bsm[i] = wp[i];
    }
    __syncthreads();

    #pragma unroll
    for (int i = 0; i < 4; i++) {
        int u = tid + (i << 9);
        int row = u >> 3, ch = u & 7;
        int orig = s_orig[row];
        const float4* src = (const float4*)(ea + (size_t)orig * 64 + ch * 8);
        float4 v0 = src[0], v1 = src[1];
        float vv[8] = {v0.x, v0.y, v0.z, v0.w, v1.x, v1.y, v1.z, v1.w};
        uint4 hq, lq; split8(vv, hq, lq);
        int off = row * 144 + ch * 16;
        *(uint4*)(sm + S_AHI + off) = hq;
        *(uint4*)(sm + S_ALO + off) = lq;
    }
    __syncthreads();

    float acc[8][4];
    #pragma unroll
    for (int nj = 0; nj < 8; nj++)
        #pragma unroll
        for (int c = 0; c < 4; c++) acc[nj][c] = 0.f;

    #pragma unroll
    for (int pass = 0; pass < 3; pass++) {
        uint32_t Ab = sb + ((pass < 2) ? S_AHI : S_ALO);
        uint32_t Bb = sb + ((pass == 1) ? S_BLO : S_BHI);
        #pragma unroll
        for (int kb = 0; kb < 4; kb++) {
            uint32_t a0, a1, a2, a3;
            {
                int row = wid * 16 + (lane & 15);
                int k = kb * 16 + ((lane & 16) ? 8 : 0);
                ldsm_x4(a0, a1, a2, a3, Ab + row * 144 + k * 2);
            }
            #pragma unroll
            for (int njp = 0; njp < 4; njp++) {
                int n = njp * 16 + ((lane & 16) ? 8 : 0) + (lane & 7);
                int k = kb * 16 + ((lane & 8) ? 8 : 0);
                uint32_t b0r, b1r, b2r, b3r;
                ldsm_x4(b0r, b1r, b2r, b3r, Bb + n * 144 + k * 2);
                mma_bf16(acc[2 * njp][0], acc[2 * njp][1], acc[2 * njp][2], acc[2 * njp][3],
                         a0, a1, a2, a3, b0r, b1r);
                mma_bf16(acc[2 * njp + 1][0], acc[2 * njp + 1][1], acc[2 * njp + 1][2], acc[2 * njp + 1][3],
                         a0, a1, a2, a3, b2r, b3r);
            }
        }
    }

    int q = lane >> 2, r4 = lane & 3;
    int rowA = wid * 16 + q;
    int2 eA = s_edge[rowA];
    int2 eB = s_edge[rowA + 8];
    const float* xlA = g_xl + (size_t)eA.x * 64;
    const float* xrA = g_xr + (size_t)eA.y * 64;
    const float* xlB = g_xl + (size_t)eB.x * 64;
    const float* xrB = g_xr + (size_t)eB.y * 64;

    float p0 = 0.f, p1 = 0.f;
    #pragma unroll
    for (int nj = 0; nj < 8; nj++) {
        int n = nj * 8 + 2 * r4;
        float a0 = s_att[n], a1 = s_att[n + 1];
        float2 la = *(const float2*)(xlA + n);
        float2 ra = *(const float2*)(xrA + n);
        float2 lb = *(const float2*)(xlB + n);
        float2 rb = *(const float2*)(xrB + n);
        float v;
        v = acc[nj][0] + la.x + ra.x; p0 += fmaxf(v, NEG_SLOPE * v) * a0;
        v = acc[nj][1] + la.y + ra.y; p0 += fmaxf(v, NEG_SLOPE * v) * a1;
        v = acc[nj][2] + lb.x + rb.x; p1 += fmaxf(v, NEG_SLOPE * v) * a0;
        v = acc[nj][3] + lb.y + rb.y; p1 += fmaxf(v, NEG_SLOPE * v) * a1;
    }
    p0 += __shfl_xor_sync(0xffffffffu, p0, 1);
    p0 += __shfl_xor_sync(0xffffffffu, p0, 2);
    p1 += __shfl_xor_sync(0xffffffffu, p1, 1);
    p1 += __shfl_xor_sync(0xffffffffu, p1, 2);
    if (r4 == 0) {
        g_score[r0 + rowA]     = p0;
        g_score[r0 + rowA + 8] = p1;
    }
}

// ---------------- per-node softmax + gather + relu + instnorm ----------------
// warp per node; 4 edge sub-groups of 8 lanes (4x MLP in the gather phase)
__global__ void aggregate_kernel(const float* __restrict__ bo,
                                 int useskip, float* out_ext)
{
    __shared__ float s_a[8][32];
    __shared__ int   s_s[8][32];
    float* out = out_ext ? out_ext : g_h;
    int tid = threadIdx.x;
    int w = tid >> 5, l = tid & 31;
    int n = blockIdx.x * 8 + w;
    if (n >= NNODES) return;

    int r0 = g_rowptr[n], r1 = g_rowptr[n + 1];

    float mx = -3.402823466e38f;
    for (int i = r0 + l; i < r1; i += 32) mx = fmaxf(mx, g_score[i]);
    #pragma unroll
    for (int o = 16; o > 0; o >>= 1) mx = fmaxf(mx, __shfl_xor_sync(0xffffffffu, mx, o));

    float ss = 0.f;
    for (int i = r0 + l; i < r1; i += 32) ss += __expf(g_score[i] - mx);
    #pragma unroll
    for (int o = 16; o > 0; o >>= 1) ss += __shfl_xor_sync(0xffffffffu, ss, o);
    float inv = 1.f / (ss + 1e-16f);

    int sub = l >> 3;        // 0..3: edge sub-group
    int wl  = l & 7;         // 0..7: column octet
    float acc[8];
    #pragma unroll
    for (int k = 0; k < 8; k++) acc[k] = 0.f;

    for (int c = r0; c < r1; c += 32) {
        int i = c + l;
        if (i < r1) {
            s_a[w][l] = __expf(g_score[i] - mx) * inv;
            s_s[w][l] = g_edge[i].x;
        }
        __syncwarp();
        int cnt = r1 - c; if (cnt > 32) cnt = 32;
        #pragma unroll 2
        for (int j0 = 0; j0 < cnt; j0 += 4) {
            int j = j0 + sub;
            if (j < cnt) {
                float a = s_a[w][j];
                const float4* xs = (const float4*)(g_xl + (size_t)s_s[w][j] * 64 + wl * 8);
                float4 v0 = __ldg(xs);
                float4 v1 = __ldg(xs + 1);
                acc[0] += a * v0.x; acc[1] += a * v0.y; acc[2] += a * v0.z; acc[3] += a * v0.w;
                acc[4] += a * v1.x; acc[5] += a * v1.y; acc[6] += a * v1.z; acc[7] += a * v1.w;
            }
        }
        __syncwarp();
    }

    // fold the 4 edge sub-groups (lanes l, l+8, l+16, l+24 share wl)
    #pragma unroll
    for (int k = 0; k < 8; k++) {
        acc[k] += __shfl_xor_sync(0xffffffffu, acc[k], 8);
        acc[k] += __shfl_xor_sync(0xffffffffu, acc[k], 16);
    }

    // bias + skip + relu on cols wl*8..wl*8+7 (replicated across sub)
    float v[8];
    {
        const float4* bp = (const float4*)(bo + wl * 8);
        float4 b0 = bp[0], b1 = bp[1];
        v[0] = acc[0] + b0.x; v[1] = acc[1] + b0.y; v[2] = acc[2] + b0.z; v[3] = acc[3] + b0.w;
        v[4] = acc[4] + b1.x; v[5] = acc[5] + b1.y; v[6] = acc[6] + b1.z; v[7] = acc[7] + b1.w;
        if (useskip) {
            const float4* sp = (const float4*)(g_skip + (size_t)n * 64 + wl * 8);
            float4 s0 = sp[0], s1 = sp[1];
            v[0] += s0.x; v[1] += s0.y; v[2] += s0.z; v[3] += s0.w;
            v[4] += s1.x; v[5] += s1.y; v[6] += s1.z; v[7] += s1.w;
        }
        #pragma unroll
        for (int k = 0; k < 8; k++) v[k] = fmaxf(v[k], 0.f);
    }

    // instance norm over 64 cols: butterfly over the 8 wl lanes (sub-replicated)
    float t = 0.f;
    #pragma unroll
    for (int k = 0; k < 8; k++) t += v[k];
    t += __shfl_xor_sync(0xffffffffu, t, 1);
    t += __shfl_xor_sync(0xffffffffu, t, 2);
    t += __shfl_xor_sync(0xffffffffu, t, 4);
    float mu = t * (1.f / 64.f);

    float qv = 0.f;
    #pragma unroll
    for (int k = 0; k < 8; k++) { v[k] -= mu; qv += v[k] * v[k]; }
    qv += __shfl_xor_sync(0xffffffffu, qv, 1);
    qv += __shfl_xor_sync(0xffffffffu, qv, 2);
    qv += __shfl_xor_sync(0xffffffffu, qv, 4);
    float sc = rsqrtf(qv * (1.f / 64.f) + EPS_IN);

    if (sub == 0) {
        float4* op = (float4*)(out + (size_t)n * 64 + wl * 8);
        op[0] = make_float4(v[0] * sc, v[1] * sc, v[2] * sc, v[3] * sc);
        op[1] = make_float4(v[4] * sc, v[5] * sc, v[6] * sc, v[7] * sc);
    }
}

// ---------------- launch ----------------
extern "C" void kernel_launch(void* const* d_in, const int* in_sizes, int n_in,
                              void* d_out, int out_size) {
    const float* x     = (const float*)d_in[0];
    const void*  ei    = d_in[1];
    const float* ea    = (const float*)d_in[2];
    const float* Wl1   = (const float*)d_in[3];
    const float* bl1   = (const float*)d_in[4];
    const float* Wr1   = (const float*)d_in[5];
    const float* br1   = (const float*)d_in[6];
    const float* We1   = (const float*)d_in[7];
    const float* att1  = (const float*)d_in[8];
    const float* bo1   = (const float*)d_in[9];
    const float* Wl2   = (const float*)d_in[10];
    const float* bl2   = (const float*)d_in[11];
    const float* Wr2   = (const float*)d_in[12];
    const float* br2   = (const float*)d_in[13];
    const float* We2   = (const float*)d_in[14];
    const float* att2  = (const float*)d_in[15];
    const float* bo2   = (const float*)d_in[16];
    const float* Wskip = (const float*)d_in[17];
    const float* bskip = (const float*)d_in[18];
    float* out = (float*)d_out;

    cudaFuncSetAttribute(lin_mma_kernel,   cudaFuncAttributeMaxDynamicSharedMemorySize, SMEM_LINM);
    cudaFuncSetAttribute(score_mma_kernel, cudaFuncAttributeMaxDynamicSharedMemorySize, SMEM_SCORE);

    const int EB = (NEDGES + 255) / 256;
    const int NT = (NNODES + 127) / 128;
    const int ET = NEDGES / 256;   // 6250, exact

    // weight slots: 0=Wl1 1=Wr1 2=Wskip 3=We1 4=Wl2 5=Wr2 6=We2
    prep_kernel<<<391, 256>>>((const int*)ei, Wl1, Wr1, Wskip, We1, Wl2, Wr2, We2);    // 1
    convert_count_kernel<<<EB, 256>>>(ei);                                              // 2
    scan_kernel<<<1, 1024>>>();                                                         // 3
    place_kernel<<<EB, 256>>>();                                                        // 4 (profiled)
    lin_mma_kernel<<<NT, 128, SMEM_LINM>>>(x, 0, 3, 0, bl1, br1, bskip, NNODES);        // 5
    score_mma_kernel<<<ET, 512, SMEM_SCORE>>>(ea, 3, att1);                             // 6
    aggregate_kernel<<<(NNODES + 7) / 8, 256>>>(bo1, 0, nullptr);                       // 7
    lin_mma_kernel<<<NT, 128, SMEM_LINM>>>(nullptr, 1, 2, 4, bl2, br2, nullptr, NNODES);// 8
    score_mma_kernel<<<ET, 512, SMEM_SCORE>>>(ea, 6, att2);                             // 9
    aggregate_kernel<<<(NNODES + 7) / 8, 256>>>(bo2, 1, out);                           // 10
}